// round 5
// baseline (speedup 1.0000x reference)
#include <cuda_runtime.h>
#include <cuda_bf16.h>
#include <cstdint>
#include <cstddef>

// ---------------- problem constants ----------------
#define B_    32
#define NTOK  3136
#define C_    512
#define NH    8
#define S_    49
#define G_    64
#define M_    (B_*G_*S_)    // 100352 (784*128)
#define QKVN  1536
#define SCALE_ 0.125f
#define L2T_OVER16 0.8304820237218406f

// ---------------- scratch ----------------
__device__ float g_qkv[(size_t)M_ * QKVN];           // fp32 qkv (roped), (b,g,s) rows
__device__ __nv_bfloat16 g_xhi[(size_t)M_ * C_];     // gathered x, split
__device__ __nv_bfloat16 g_xlo[(size_t)M_ * C_];
__device__ __nv_bfloat16 g_whi[QKVN * C_];
__device__ __nv_bfloat16 g_wlo[QKVN * C_];
__device__ __nv_bfloat16 g_phi[C_ * C_];
__device__ __nv_bfloat16 g_plo[C_ * C_];
__device__ __nv_bfloat16 g_ahi[(size_t)M_ * C_];     // attention out, split, (b,n) rows
__device__ __nv_bfloat16 g_alo[(size_t)M_ * C_];

// row r (in b,g,s order) -> x row offset (b,n)
__device__ __forceinline__ size_t gather_row_off(int r) {
    int b   = r / (G_ * S_);
    int rem = r - b * (G_ * S_);
    int g   = rem / S_;
    int s   = rem - g * S_;
    int sy  = s / 7;
    int sx  = s - sy * 7;
    int n   = ((g >> 3) * 7 + sy) * 56 + (g & 7) * 7 + sx;
    return ((size_t)b * NTOK + n) * C_;
}

// ---------------- asm wrappers ----------------
__device__ __forceinline__ uint32_t smem_u32(const void* p) {
    uint32_t a;
    asm("{ .reg .u64 t; cvta.to.shared.u64 t, %1; cvt.u32.u64 %0, t; }" : "=r"(a) : "l"(p));
    return a;
}
__device__ __forceinline__ void cp16(uint32_t saddr, const void* g) {
    asm volatile("cp.async.cg.shared.global [%0], [%1], 16;" :: "r"(saddr), "l"(g));
}
__device__ __forceinline__ void cp_commit() {
    asm volatile("cp.async.commit_group;" ::: "memory");
}
__device__ __forceinline__ void cp_wait0() {
    asm volatile("cp.async.wait_group 0;" ::: "memory");
}
__device__ __forceinline__ void cp_wait1() {
    asm volatile("cp.async.wait_group 1;" ::: "memory");
}
__device__ __forceinline__ void ldm4(uint32_t* r, uint32_t addr) {
    asm volatile("ldmatrix.sync.aligned.m8n8.x4.shared.b16 {%0,%1,%2,%3}, [%4];"
        : "=r"(r[0]), "=r"(r[1]), "=r"(r[2]), "=r"(r[3]) : "r"(addr));
}
__device__ __forceinline__ void mma16816(float* c, const uint32_t* a, const uint32_t* b) {
    asm volatile("mma.sync.aligned.m16n8k16.row.col.f32.bf16.bf16.f32 "
        "{%0,%1,%2,%3}, {%4,%5,%6,%7}, {%8,%9}, {%0,%1,%2,%3};"
        : "+f"(c[0]), "+f"(c[1]), "+f"(c[2]), "+f"(c[3])
        : "r"(a[0]), "r"(a[1]), "r"(a[2]), "r"(a[3]), "r"(b[0]), "r"(b[1]));
}

// ---------------- conversion kernels ----------------
__global__ __launch_bounds__(256) void conv_x_kernel(const float* __restrict__ x) {
    int idx = blockIdx.x * 256 + threadIdx.x;       // M_*128 threads
    int r = idx >> 7;
    int q = (idx & 127) << 2;
    float4 v = *(const float4*)(x + gather_row_off(r) + q);
    float vv[4] = {v.x, v.y, v.z, v.w};
    uint32_t hp[2], lp[2];
    #pragma unroll
    for (int p = 0; p < 2; p++) {
        __nv_bfloat162 h2, l2;
        h2.x = __float2bfloat16_rn(vv[2*p]);
        h2.y = __float2bfloat16_rn(vv[2*p+1]);
        l2.x = __float2bfloat16_rn(vv[2*p]   - __bfloat162float(h2.x));
        l2.y = __float2bfloat16_rn(vv[2*p+1] - __bfloat162float(h2.y));
        hp[p] = *(uint32_t*)&h2;
        lp[p] = *(uint32_t*)&l2;
    }
    size_t o = (size_t)r * C_ + q;
    *(uint2*)(g_xhi + o) = make_uint2(hp[0], hp[1]);
    *(uint2*)(g_xlo + o) = make_uint2(lp[0], lp[1]);
}

__global__ __launch_bounds__(256) void conv_w_kernel(const float* __restrict__ w,
                                                     __nv_bfloat16* __restrict__ hi,
                                                     __nv_bfloat16* __restrict__ lo) {
    int idx = blockIdx.x * 256 + threadIdx.x;
    size_t o = (size_t)idx << 2;
    float4 v = *(const float4*)(w + o);
    float vv[4] = {v.x, v.y, v.z, v.w};
    uint32_t hp[2], lp[2];
    #pragma unroll
    for (int p = 0; p < 2; p++) {
        __nv_bfloat162 h2, l2;
        h2.x = __float2bfloat16_rn(vv[2*p]);
        h2.y = __float2bfloat16_rn(vv[2*p+1]);
        l2.x = __float2bfloat16_rn(vv[2*p]   - __bfloat162float(h2.x));
        l2.y = __float2bfloat16_rn(vv[2*p+1] - __bfloat162float(h2.y));
        hp[p] = *(uint32_t*)&h2;
        lp[p] = *(uint32_t*)&l2;
    }
    *(uint2*)(hi + o) = make_uint2(hp[0], hp[1]);
    *(uint2*)(lo + o) = make_uint2(lp[0], lp[1]);
}

// ---------------- split-bf16 HMMA GEMM ----------------
// C[r][d] = sum_k A[r][k]*B[d][k] (+bias / +rope), K=512
// block 128x128, 4 warps (2x2), warp tile 64x64, BK=32, 3-stage cp.async
// Tiles row-paired: 2 logical rows (64B) per 128B physical row, SW128 xor swizzle.
#define STG_BYTES 32768u   // 4 matrices x 64 phys rows x 128B
#define NSTG 3
#define DYN_SMEM (NSTG * STG_BYTES)

template <int NCOLS, bool BIAS, bool ROPE>
__global__ __launch_bounds__(128, 2) void mma_gemm(
    const __nv_bfloat16* __restrict__ Ahi, const __nv_bfloat16* __restrict__ Alo,
    const __nv_bfloat16* __restrict__ Bhi, const __nv_bfloat16* __restrict__ Blo,
    const float* __restrict__ bias, float* __restrict__ Cc)
{
    extern __shared__ __align__(1024) char dyn[];
    const uint32_t sbase = smem_u32(dyn);

    const int tid  = threadIdx.x;
    const int lane = tid & 31;
    const int wid  = tid >> 5;
    const int wm   = wid >> 1;          // 0..1
    const int wn   = wid & 1;           // 0..1
    const int bm   = blockIdx.y * 128;
    const int bn   = blockIdx.x * 128;

    // ---- loader: 4 groups of 32 threads, one matrix each; 2 phys rows/thread ----
    const int grp  = tid >> 5;          // 0:Ahi 1:Alo 2:Bhi 3:Blo
    const int pr0  = tid & 31;
    const __nv_bfloat16* gsrc;
    if      (grp == 0) gsrc = Ahi + (size_t)bm * C_;
    else if (grp == 1) gsrc = Alo + (size_t)bm * C_;
    else if (grp == 2) gsrc = Bhi + (size_t)bn * C_;
    else               gsrc = Blo + (size_t)bn * C_;
    const uint32_t smat = sbase + grp * 8192u;

    auto load_stage = [&](int st, int kc) {
        #pragma unroll
        for (int rr = 0; rr < 2; rr++) {
            int pr = pr0 + rr * 32;
            const char* g0 = (const char*)(gsrc + (size_t)(2 * pr) * C_ + kc * 32);
            uint32_t rb = smat + (uint32_t)st * STG_BYTES + (uint32_t)pr * 128u;
            int sx = pr & 7;
            #pragma unroll
            for (int c = 0; c < 8; c++)
                cp16(rb + (uint32_t)((c ^ sx) << 4), g0 + (c >> 2) * (C_ * 2) + (c & 3) * 16);
        }
    };

    // ---- fragment address components ----
    const int a_r  = wm * 64 + (lane & 15);
    const int a_cp = lane >> 4;
    const int b_r0 = wn * 64 + (lane & 7) + ((lane & 16) >> 1);
    const int b_cp = (lane >> 3) & 1;

    float acc[4][8][4];
    #pragma unroll
    for (int i = 0; i < 4; i++)
        #pragma unroll
        for (int j = 0; j < 8; j++)
            #pragma unroll
            for (int p = 0; p < 4; p++) acc[i][j][p] = 0.0f;

    load_stage(0, 0); cp_commit();
    load_stage(1, 1); cp_commit();

    #pragma unroll 1
    for (int kc = 0; kc < 16; kc++) {
        if (kc < 15) cp_wait1(); else cp_wait0();
        __syncthreads();
        if (kc + 2 < 16) { load_stage((kc + 2) % NSTG, kc + 2); cp_commit(); }

        const uint32_t base = sbase + (uint32_t)(kc % NSTG) * STG_BYTES;
        #pragma unroll
        for (int ks = 0; ks < 2; ks++) {
            uint32_t ah[4][4], al[4][4], bh[4][4], bl[4][4];
            const int ch4 = 2 * ks;
            #pragma unroll
            for (int i = 0; i < 4; i++) {
                int r  = a_r + i * 16;
                int pr = r >> 1;
                int pc = ((r & 1) << 2) + ch4 + a_cp;
                uint32_t ad = base + (uint32_t)(pr * 128 + ((pc ^ (pr & 7)) << 4));
                ldm4(ah[i], ad);
                ldm4(al[i], ad + 8192u);
            }
            #pragma unroll
            for (int jj = 0; jj < 4; jj++) {
                int r  = b_r0 + jj * 16;
                int pr = r >> 1;
                int pc = ((r & 1) << 2) + ch4 + b_cp;
                uint32_t ad = base + 16384u + (uint32_t)(pr * 128 + ((pc ^ (pr & 7)) << 4));
                ldm4(bh[jj], ad);
                ldm4(bl[jj], ad + 8192u);
            }
            #pragma unroll
            for (int i = 0; i < 4; i++)
                #pragma unroll
                for (int j = 0; j < 8; j++) {
                    const uint32_t* bhp = &bh[j >> 1][(j & 1) * 2];
                    const uint32_t* blp = &bl[j >> 1][(j & 1) * 2];
                    mma16816(acc[i][j], ah[i], bhp);
                    mma16816(acc[i][j], al[i], bhp);
                    mma16816(acc[i][j], ah[i], blp);
                }
        }
    }

    // ---- epilogue (optionally fused 2D RoPE) ----
    const int orow = bm + wm * 64 + (lane >> 2);
    const int ocol = bn + wn * 64 + (lane & 3) * 2;
    #pragma unroll
    for (int i = 0; i < 4; i++) {
        const int rA = orow + i * 16;
        const int rB = rA + 8;
        int sA = 0, sB = 0;
        if (ROPE) { sA = rA % S_; sB = rB % S_; }
        #pragma unroll
        for (int j = 0; j < 8; j++) {
            const int cc = ocol + j * 8;
            float v0 = acc[i][j][0], v1 = acc[i][j][1];
            float v2 = acc[i][j][2], v3 = acc[i][j][3];
            if (ROPE && cc < 1024) {
                int m = (cc & 63) >> 1;
                float freq = exp2f(-(float)(m >> 1) * L2T_OVER16);
                float pA = (m & 1) ? (float)(sA / 7) : (float)(sA % 7);
                float pB = (m & 1) ? (float)(sB / 7) : (float)(sB % 7);
                float snA, csA, snB, csB;
                sincosf(pA * freq, &snA, &csA);
                sincosf(pB * freq, &snB, &csB);
                float t0 = v0 * csA - v1 * snA, t1 = v0 * snA + v1 * csA;
                float t2 = v2 * csB - v3 * snB, t3 = v2 * snB + v3 * csB;
                v0 = t0; v1 = t1; v2 = t2; v3 = t3;
            }
            if (BIAS) {
                float bx = bias[cc], by = bias[cc + 1];
                v0 += bx; v1 += by; v2 += bx; v3 += by;
            }
            *(float2*)(Cc + (size_t)rA * NCOLS + cc) = make_float2(v0, v1);
            *(float2*)(Cc + (size_t)rB * NCOLS + cc) = make_float2(v2, v3);
        }
    }
}

// ---------------- windowed attention (writes split bf16) ----------------
__global__ __launch_bounds__(256) void attn_kernel() {
    __shared__ float qs[49 * 68];
    __shared__ float ks[49 * 68];
    __shared__ float vs[49 * 64];
    __shared__ float sc[49 * 49];

    const int tid = threadIdx.x;
    const int h   = blockIdx.x & 7;
    const int bg  = blockIdx.x >> 3;

    const size_t base = (size_t)bg * S_ * QKVN + h * 64;

    for (int i = tid; i < 49 * 16; i += 256) {
        int s  = i >> 4;
        int d4 = (i & 15) * 4;
        size_t ro = base + (size_t)s * QKVN + d4;
        float4 q = *(const float4*)(g_qkv + ro);
        float4 k = *(const float4*)(g_qkv + ro + 512);
        float4 v = *(const float4*)(g_qkv + ro + 1024);
        *(float4*)&qs[s * 68 + d4] = q;
        *(float4*)&ks[s * 68 + d4] = k;
        *(float4*)&vs[s * 64 + d4] = v;
    }
    __syncthreads();

    for (int p = tid; p < 49 * 49; p += 256) {
        int s  = p / 49;
        int tt = p - s * 49;
        const float* qp = &qs[s * 68];
        const float* kp = &ks[tt * 68];
        float acc = 0.0f;
        #pragma unroll
        for (int d = 0; d < 64; d += 4) {
            float4 a = *(const float4*)(qp + d);
            float4 b = *(const float4*)(kp + d);
            acc += a.x * b.x + a.y * b.y + a.z * b.z + a.w * b.w;
        }
        sc[p] = acc * SCALE_;
    }
    __syncthreads();

    const int warp = tid >> 5, lane = tid & 31;
    for (int row = warp; row < 49; row += 8) {
        float mx = -1e30f;
        for (int t = lane; t < 49; t += 32) mx = fmaxf(mx, sc[row * 49 + t]);
        #pragma unroll
        for (int o = 16; o > 0; o >>= 1) mx = fmaxf(mx, __shfl_xor_sync(0xffffffffu, mx, o));
        float sum = 0.0f;
        for (int t = lane; t < 49; t += 32) {
            float e = __expf(sc[row * 49 + t] - mx);
            sc[row * 49 + t] = e;
            sum += e;
        }
        #pragma unroll
        for (int o = 16; o > 0; o >>= 1) sum += __shfl_xor_sync(0xffffffffu, sum, o);
        float inv = 1.0f / sum;
        for (int t = lane; t < 49; t += 32) sc[row * 49 + t] *= inv;
    }
    __syncthreads();

    const int g = bg & 63;
    const int b = bg >> 6;
    for (int o = tid; o < 49 * 64; o += 256) {
        int s = o >> 6;
        int d = o & 63;
        const float* sr = &sc[s * 49];
        float acc = 0.0f;
        #pragma unroll
        for (int tt = 0; tt < 49; tt++)
            acc = fmaf(sr[tt], vs[tt * 64 + d], acc);
        int sy = s / 7, sx = s - sy * 7;
        int n  = ((g >> 3) * 7 + sy) * 56 + (g & 7) * 7 + sx;
        size_t off = ((size_t)(b * NTOK + n)) * C_ + h * 64 + d;
        __nv_bfloat16 hv = __float2bfloat16_rn(acc);
        g_ahi[off] = hv;
        g_alo[off] = __float2bfloat16_rn(acc - __bfloat162float(hv));
    }
}

// ---------------- launch ----------------
extern "C" void kernel_launch(void* const* d_in, const int* in_sizes, int n_in,
                              void* d_out, int out_size)
{
    const float* x      = (const float*)d_in[0];
    const float* w_qkv  = (const float*)d_in[1];
    const float* w_proj = (const float*)d_in[2];
    const float* b_proj = (const float*)d_in[3];
    float* out = (float*)d_out;

    void *qkvp, *xhip, *xlop, *whip, *wlop, *phip, *plop, *ahip, *alop;
    cudaGetSymbolAddress(&qkvp, g_qkv);
    cudaGetSymbolAddress(&xhip, g_xhi); cudaGetSymbolAddress(&xlop, g_xlo);
    cudaGetSymbolAddress(&whip, g_whi); cudaGetSymbolAddress(&wlop, g_wlo);
    cudaGetSymbolAddress(&phip, g_phi); cudaGetSymbolAddress(&plop, g_plo);
    cudaGetSymbolAddress(&ahip, g_ahi); cudaGetSymbolAddress(&alop, g_alo);

    cudaFuncSetAttribute(mma_gemm<QKVN, false, true>,
                         cudaFuncAttributeMaxDynamicSharedMemorySize, DYN_SMEM);
    cudaFuncSetAttribute(mma_gemm<C_, true, false>,
                         cudaFuncAttributeMaxDynamicSharedMemorySize, DYN_SMEM);

    // 0) conversions
    conv_x_kernel<<<M_ * 128 / 256, 256>>>(x);
    conv_w_kernel<<<QKVN * 128 / 256, 256>>>(w_qkv, (__nv_bfloat16*)whip, (__nv_bfloat16*)wlop);
    conv_w_kernel<<<C_ * 128 / 256, 256>>>(w_proj, (__nv_bfloat16*)phip, (__nv_bfloat16*)plop);

    // 1) QKV GEMM (split-bf16 HMMA) with fused RoPE in epilogue
    dim3 g1(QKVN / 128, M_ / 128);
    mma_gemm<QKVN, false, true><<<g1, 128, DYN_SMEM>>>(
        (const __nv_bfloat16*)xhip, (const __nv_bfloat16*)xlop,
        (const __nv_bfloat16*)whip, (const __nv_bfloat16*)wlop,
        nullptr, (float*)qkvp);

    // 2) windowed attention
    attn_kernel<<<B_ * G_ * NH, 256>>>();

    // 3) projection GEMM + bias
    dim3 g2(C_ / 128, M_ / 128);
    mma_gemm<C_, true, false><<<g2, 128, DYN_SMEM>>>(
        (const __nv_bfloat16*)ahip, (const __nv_bfloat16*)alop,
        (const __nv_bfloat16*)phip, (const __nv_bfloat16*)plop,
        b_proj, out);
}

// round 6
// speedup vs baseline: 1.6653x; 1.6653x over previous
#include <cuda_runtime.h>
#include <cuda_bf16.h>
#include <cstdint>
#include <cstddef>

// ---------------- problem constants ----------------
#define B_    32
#define NTOK  3136
#define C_    512
#define NH    8
#define S_    49
#define G_    64
#define M_    (B_*G_*S_)    // 100352 (784*128)
#define QKVN  1536
#define SCALE_ 0.125f
#define L2T_OVER16 0.8304820237218406f

// ---------------- scratch ----------------
__device__ float g_qkv[(size_t)M_ * QKVN];           // fp32 qkv (roped), (b,g,s) rows
__device__ __nv_bfloat16 g_xhi[(size_t)M_ * C_];     // gathered x, split
__device__ __nv_bfloat16 g_xlo[(size_t)M_ * C_];
__device__ __nv_bfloat16 g_whi[QKVN * C_];
__device__ __nv_bfloat16 g_wlo[QKVN * C_];
__device__ __nv_bfloat16 g_phi[C_ * C_];
__device__ __nv_bfloat16 g_plo[C_ * C_];
__device__ __nv_bfloat16 g_ahi[(size_t)M_ * C_];     // attention out, split, (b,n) rows
__device__ __nv_bfloat16 g_alo[(size_t)M_ * C_];

// row r (in b,g,s order) -> x row offset (b,n)
__device__ __forceinline__ size_t gather_row_off(int r) {
    int b   = r / (G_ * S_);
    int rem = r - b * (G_ * S_);
    int g   = rem / S_;
    int s   = rem - g * S_;
    int sy  = s / 7;
    int sx  = s - sy * 7;
    int n   = ((g >> 3) * 7 + sy) * 56 + (g & 7) * 7 + sx;
    return ((size_t)b * NTOK + n) * C_;
}

// ---------------- asm wrappers ----------------
__device__ __forceinline__ uint32_t smem_u32(const void* p) {
    uint32_t a;
    asm("{ .reg .u64 t; cvta.to.shared.u64 t, %1; cvt.u32.u64 %0, t; }" : "=r"(a) : "l"(p));
    return a;
}
__device__ __forceinline__ void cp16(uint32_t saddr, const void* g) {
    asm volatile("cp.async.cg.shared.global [%0], [%1], 16;" :: "r"(saddr), "l"(g));
}
__device__ __forceinline__ void cp_commit() {
    asm volatile("cp.async.commit_group;" ::: "memory");
}
__device__ __forceinline__ void cp_wait0() {
    asm volatile("cp.async.wait_group 0;" ::: "memory");
}
__device__ __forceinline__ void cp_wait1() {
    asm volatile("cp.async.wait_group 1;" ::: "memory");
}
__device__ __forceinline__ void ldm4(uint32_t* r, uint32_t addr) {
    asm volatile("ldmatrix.sync.aligned.m8n8.x4.shared.b16 {%0,%1,%2,%3}, [%4];"
        : "=r"(r[0]), "=r"(r[1]), "=r"(r[2]), "=r"(r[3]) : "r"(addr));
}
__device__ __forceinline__ void mma16816(float* c, const uint32_t* a, const uint32_t* b) {
    asm volatile("mma.sync.aligned.m16n8k16.row.col.f32.bf16.bf16.f32 "
        "{%0,%1,%2,%3}, {%4,%5,%6,%7}, {%8,%9}, {%0,%1,%2,%3};"
        : "+f"(c[0]), "+f"(c[1]), "+f"(c[2]), "+f"(c[3])
        : "r"(a[0]), "r"(a[1]), "r"(a[2]), "r"(a[3]), "r"(b[0]), "r"(b[1]));
}

// ---------------- conversion kernels ----------------
__global__ __launch_bounds__(256) void conv_x_kernel(const float* __restrict__ x) {
    int idx = blockIdx.x * 256 + threadIdx.x;       // M_*128 threads
    int r = idx >> 7;
    int q = (idx & 127) << 2;
    float4 v = *(const float4*)(x + gather_row_off(r) + q);
    float vv[4] = {v.x, v.y, v.z, v.w};
    uint32_t hp[2], lp[2];
    #pragma unroll
    for (int p = 0; p < 2; p++) {
        __nv_bfloat162 h2, l2;
        h2.x = __float2bfloat16_rn(vv[2*p]);
        h2.y = __float2bfloat16_rn(vv[2*p+1]);
        l2.x = __float2bfloat16_rn(vv[2*p]   - __bfloat162float(h2.x));
        l2.y = __float2bfloat16_rn(vv[2*p+1] - __bfloat162float(h2.y));
        hp[p] = *(uint32_t*)&h2;
        lp[p] = *(uint32_t*)&l2;
    }
    size_t o = (size_t)r * C_ + q;
    *(uint2*)(g_xhi + o) = make_uint2(hp[0], hp[1]);
    *(uint2*)(g_xlo + o) = make_uint2(lp[0], lp[1]);
}

__global__ __launch_bounds__(256) void conv_w_kernel(const float* __restrict__ w,
                                                     __nv_bfloat16* __restrict__ hi,
                                                     __nv_bfloat16* __restrict__ lo) {
    int idx = blockIdx.x * 256 + threadIdx.x;
    size_t o = (size_t)idx << 2;
    float4 v = *(const float4*)(w + o);
    float vv[4] = {v.x, v.y, v.z, v.w};
    uint32_t hp[2], lp[2];
    #pragma unroll
    for (int p = 0; p < 2; p++) {
        __nv_bfloat162 h2, l2;
        h2.x = __float2bfloat16_rn(vv[2*p]);
        h2.y = __float2bfloat16_rn(vv[2*p+1]);
        l2.x = __float2bfloat16_rn(vv[2*p]   - __bfloat162float(h2.x));
        l2.y = __float2bfloat16_rn(vv[2*p+1] - __bfloat162float(h2.y));
        hp[p] = *(uint32_t*)&h2;
        lp[p] = *(uint32_t*)&l2;
    }
    *(uint2*)(hi + o) = make_uint2(hp[0], hp[1]);
    *(uint2*)(lo + o) = make_uint2(lp[0], lp[1]);
}

// ---------------- split-bf16 HMMA GEMM ----------------
// C[r][d] = sum_k A[r][k]*B[d][k] (+bias / +rope), K=512
// block 128x128, 8 warps (2x4), warp tile 64x32, BK=32, 3-stage cp.async
// Tiles row-paired: 2 logical rows (64B) per 128B physical row, SW128 xor swizzle.
#define STG_BYTES 32768u   // 4 matrices x 64 phys rows x 128B
#define NSTG 3
#define DYN_SMEM (NSTG * STG_BYTES)

template <int NCOLS, bool BIAS, bool ROPE>
__global__ __launch_bounds__(256, 2) void mma_gemm(
    const __nv_bfloat16* __restrict__ Ahi, const __nv_bfloat16* __restrict__ Alo,
    const __nv_bfloat16* __restrict__ Bhi, const __nv_bfloat16* __restrict__ Blo,
    const float* __restrict__ bias, float* __restrict__ Cc)
{
    extern __shared__ __align__(1024) char dyn[];
    const uint32_t sbase = smem_u32(dyn);

    const int tid  = threadIdx.x;
    const int lane = tid & 31;
    const int wid  = tid >> 5;
    const int wm   = wid >> 2;          // 0..1
    const int wn   = wid & 3;           // 0..3
    const int bm   = blockIdx.y * 128;
    const int bn   = blockIdx.x * 128;

    // ---- loader: 4 groups of 64 threads, one matrix each; 1 phys row/thread ----
    const int grp  = tid >> 6;          // 0:Ahi 1:Alo 2:Bhi 3:Blo
    const int prow = tid & 63;
    const __nv_bfloat16* gsrc;
    if      (grp == 0) gsrc = Ahi + (size_t)bm * C_;
    else if (grp == 1) gsrc = Alo + (size_t)bm * C_;
    else if (grp == 2) gsrc = Bhi + (size_t)bn * C_;
    else               gsrc = Blo + (size_t)bn * C_;
    const __nv_bfloat16* grow = gsrc + (size_t)(2 * prow) * C_;
    const uint32_t smat = sbase + grp * 8192u + prow * 128u;
    const int sx = prow & 7;

    auto load_stage = [&](int st, int kc) {
        const char* g0 = (const char*)(grow + kc * 32);
        uint32_t rb = smat + (uint32_t)st * STG_BYTES;
        #pragma unroll
        for (int c = 0; c < 8; c++)
            cp16(rb + (uint32_t)((c ^ sx) << 4), g0 + (c >> 2) * (C_ * 2) + (c & 3) * 16);
    };

    // ---- fragment smem offsets (stage-relative), precomputed per ks ----
    const int a_r  = wm * 64 + (lane & 15);
    const int a_cp = lane >> 4;
    const int b_r0 = wn * 32 + (lane & 7) + ((lane & 16) >> 1);
    const int b_cp = (lane >> 3) & 1;

    uint32_t aoff[2][4], boff[2][2];
    #pragma unroll
    for (int ks = 0; ks < 2; ks++) {
        #pragma unroll
        for (int i = 0; i < 4; i++) {
            int r  = a_r + i * 16;
            int pr = r >> 1;
            int pc = ((r & 1) << 2) + 2 * ks + a_cp;
            aoff[ks][i] = (uint32_t)(pr * 128 + ((pc ^ (pr & 7)) << 4));
        }
        #pragma unroll
        for (int jj = 0; jj < 2; jj++) {
            int r  = b_r0 + jj * 16;
            int pr = r >> 1;
            int pc = ((r & 1) << 2) + 2 * ks + b_cp;
            boff[ks][jj] = 16384u + (uint32_t)(pr * 128 + ((pc ^ (pr & 7)) << 4));
        }
    }

    float acc[4][4][4];
    #pragma unroll
    for (int i = 0; i < 4; i++)
        #pragma unroll
        for (int j = 0; j < 4; j++)
            #pragma unroll
            for (int p = 0; p < 4; p++) acc[i][j][p] = 0.0f;

    load_stage(0, 0); cp_commit();
    load_stage(1, 1); cp_commit();

    uint32_t ah[2][4][4], al[2][4][4], bh[2][2][4], bl[2][2][4];

    auto load_frags = [&](int buf, uint32_t base, int ks) {
        #pragma unroll
        for (int i = 0; i < 4; i++) {
            uint32_t ad = base + aoff[ks][i];
            ldm4(ah[buf][i], ad);
            ldm4(al[buf][i], ad + 8192u);
        }
        #pragma unroll
        for (int jj = 0; jj < 2; jj++) {
            uint32_t ad = base + boff[ks][jj];
            ldm4(bh[buf][jj], ad);
            ldm4(bl[buf][jj], ad + 8192u);
        }
    };
    auto do_mmas = [&](int buf) {
        #pragma unroll
        for (int i = 0; i < 4; i++)
            #pragma unroll
            for (int j = 0; j < 4; j++) {
                const uint32_t* bhp = &bh[buf][j >> 1][(j & 1) * 2];
                const uint32_t* blp = &bl[buf][j >> 1][(j & 1) * 2];
                mma16816(acc[i][j], ah[buf][i], bhp);
                mma16816(acc[i][j], al[buf][i], bhp);
                mma16816(acc[i][j], ah[buf][i], blp);
            }
    };

    #pragma unroll 1
    for (int kc = 0; kc < 16; kc++) {
        if (kc < 15) cp_wait1(); else cp_wait0();
        __syncthreads();
        if (kc + 2 < 16) { load_stage((kc + 2) % NSTG, kc + 2); cp_commit(); }

        const uint32_t base = sbase + (uint32_t)(kc % NSTG) * STG_BYTES;
        load_frags(0, base, 0);      // ks=0 fragments
        load_frags(1, base, 1);      // ks=1 fragments issued before ks=0 MMAs retire
        do_mmas(0);
        do_mmas(1);
    }

    // ---- epilogue (optionally fused 2D RoPE) ----
    const int orow = bm + wm * 64 + (lane >> 2);
    const int ocol = bn + wn * 32 + (lane & 3) * 2;
    float bvx[4], bvy[4];
    if (BIAS) {
        #pragma unroll
        for (int j = 0; j < 4; j++) { bvx[j] = bias[ocol + j * 8]; bvy[j] = bias[ocol + j * 8 + 1]; }
    }
    #pragma unroll
    for (int i = 0; i < 4; i++) {
        const int rA = orow + i * 16;
        const int rB = rA + 8;
        int sA = 0, sB = 0;
        if (ROPE) { sA = rA % S_; sB = rB % S_; }
        #pragma unroll
        for (int j = 0; j < 4; j++) {
            const int cc = ocol + j * 8;
            float v0 = acc[i][j][0], v1 = acc[i][j][1];
            float v2 = acc[i][j][2], v3 = acc[i][j][3];
            if (ROPE && cc < 1024) {
                int m = (cc & 63) >> 1;
                float freq = exp2f(-(float)(m >> 1) * L2T_OVER16);
                float pA = (m & 1) ? (float)(sA / 7) : (float)(sA % 7);
                float pB = (m & 1) ? (float)(sB / 7) : (float)(sB % 7);
                float snA, csA, snB, csB;
                sincosf(pA * freq, &snA, &csA);
                sincosf(pB * freq, &snB, &csB);
                float t0 = v0 * csA - v1 * snA, t1 = v0 * snA + v1 * csA;
                float t2 = v2 * csB - v3 * snB, t3 = v2 * snB + v3 * csB;
                v0 = t0; v1 = t1; v2 = t2; v3 = t3;
            }
            if (BIAS) { v0 += bvx[j]; v1 += bvy[j]; v2 += bvx[j]; v3 += bvy[j]; }
            *(float2*)(Cc + (size_t)rA * NCOLS + cc) = make_float2(v0, v1);
            *(float2*)(Cc + (size_t)rB * NCOLS + cc) = make_float2(v2, v3);
        }
    }
}

// ---------------- windowed attention (writes split bf16) ----------------
__global__ __launch_bounds__(256) void attn_kernel() {
    __shared__ float qs[49 * 68];
    __shared__ float ks[49 * 68];
    __shared__ float vs[49 * 64];
    __shared__ float sc[49 * 49];

    const int tid = threadIdx.x;
    const int h   = blockIdx.x & 7;
    const int bg  = blockIdx.x >> 3;

    const size_t base = (size_t)bg * S_ * QKVN + h * 64;

    for (int i = tid; i < 49 * 16; i += 256) {
        int s  = i >> 4;
        int d4 = (i & 15) * 4;
        size_t ro = base + (size_t)s * QKVN + d4;
        float4 q = *(const float4*)(g_qkv + ro);
        float4 k = *(const float4*)(g_qkv + ro + 512);
        float4 v = *(const float4*)(g_qkv + ro + 1024);
        *(float4*)&qs[s * 68 + d4] = q;
        *(float4*)&ks[s * 68 + d4] = k;
        *(float4*)&vs[s * 64 + d4] = v;
    }
    __syncthreads();

    for (int p = tid; p < 49 * 49; p += 256) {
        int s  = p / 49;
        int tt = p - s * 49;
        const float* qp = &qs[s * 68];
        const float* kp = &ks[tt * 68];
        float acc = 0.0f;
        #pragma unroll
        for (int d = 0; d < 64; d += 4) {
            float4 a = *(const float4*)(qp + d);
            float4 b = *(const float4*)(kp + d);
            acc += a.x * b.x + a.y * b.y + a.z * b.z + a.w * b.w;
        }
        sc[p] = acc * SCALE_;
    }
    __syncthreads();

    const int warp = tid >> 5, lane = tid & 31;
    for (int row = warp; row < 49; row += 8) {
        float mx = -1e30f;
        for (int t = lane; t < 49; t += 32) mx = fmaxf(mx, sc[row * 49 + t]);
        #pragma unroll
        for (int o = 16; o > 0; o >>= 1) mx = fmaxf(mx, __shfl_xor_sync(0xffffffffu, mx, o));
        float sum = 0.0f;
        for (int t = lane; t < 49; t += 32) {
            float e = __expf(sc[row * 49 + t] - mx);
            sc[row * 49 + t] = e;
            sum += e;
        }
        #pragma unroll
        for (int o = 16; o > 0; o >>= 1) sum += __shfl_xor_sync(0xffffffffu, sum, o);
        float inv = 1.0f / sum;
        for (int t = lane; t < 49; t += 32) sc[row * 49 + t] *= inv;
    }
    __syncthreads();

    const int g = bg & 63;
    const int b = bg >> 6;
    for (int o = tid; o < 49 * 64; o += 256) {
        int s = o >> 6;
        int d = o & 63;
        const float* sr = &sc[s * 49];
        float acc = 0.0f;
        #pragma unroll
        for (int tt = 0; tt < 49; tt++)
            acc = fmaf(sr[tt], vs[tt * 64 + d], acc);
        int sy = s / 7, sx = s - sy * 7;
        int n  = ((g >> 3) * 7 + sy) * 56 + (g & 7) * 7 + sx;
        size_t off = ((size_t)(b * NTOK + n)) * C_ + h * 64 + d;
        __nv_bfloat16 hv = __float2bfloat16_rn(acc);
        g_ahi[off] = hv;
        g_alo[off] = __float2bfloat16_rn(acc - __bfloat162float(hv));
    }
}

// ---------------- launch ----------------
extern "C" void kernel_launch(void* const* d_in, const int* in_sizes, int n_in,
                              void* d_out, int out_size)
{
    const float* x      = (const float*)d_in[0];
    const float* w_qkv  = (const float*)d_in[1];
    const float* w_proj = (const float*)d_in[2];
    const float* b_proj = (const float*)d_in[3];
    float* out = (float*)d_out;

    void *qkvp, *xhip, *xlop, *whip, *wlop, *phip, *plop, *ahip, *alop;
    cudaGetSymbolAddress(&qkvp, g_qkv);
    cudaGetSymbolAddress(&xhip, g_xhi); cudaGetSymbolAddress(&xlop, g_xlo);
    cudaGetSymbolAddress(&whip, g_whi); cudaGetSymbolAddress(&wlop, g_wlo);
    cudaGetSymbolAddress(&phip, g_phi); cudaGetSymbolAddress(&plop, g_plo);
    cudaGetSymbolAddress(&ahip, g_ahi); cudaGetSymbolAddress(&alop, g_alo);

    cudaFuncSetAttribute(mma_gemm<QKVN, false, true>,
                         cudaFuncAttributeMaxDynamicSharedMemorySize, DYN_SMEM);
    cudaFuncSetAttribute(mma_gemm<C_, true, false>,
                         cudaFuncAttributeMaxDynamicSharedMemorySize, DYN_SMEM);

    // 0) conversions
    conv_x_kernel<<<M_ * 128 / 256, 256>>>(x);
    conv_w_kernel<<<QKVN * 128 / 256, 256>>>(w_qkv, (__nv_bfloat16*)whip, (__nv_bfloat16*)wlop);
    conv_w_kernel<<<C_ * 128 / 256, 256>>>(w_proj, (__nv_bfloat16*)phip, (__nv_bfloat16*)plop);

    // 1) QKV GEMM (split-bf16 HMMA) with fused RoPE in epilogue
    dim3 g1(QKVN / 128, M_ / 128);
    mma_gemm<QKVN, false, true><<<g1, 256, DYN_SMEM>>>(
        (const __nv_bfloat16*)xhip, (const __nv_bfloat16*)xlop,
        (const __nv_bfloat16*)whip, (const __nv_bfloat16*)wlop,
        nullptr, (float*)qkvp);

    // 2) windowed attention
    attn_kernel<<<B_ * G_ * NH, 256>>>();

    // 3) projection GEMM + bias
    dim3 g2(C_ / 128, M_ / 128);
    mma_gemm<C_, true, false><<<g2, 256, DYN_SMEM>>>(
        (const __nv_bfloat16*)ahip, (const __nv_bfloat16*)alop,
        (const __nv_bfloat16*)phip, (const __nv_bfloat16*)plop,
        b_proj, out);
}

// round 7
// speedup vs baseline: 2.1021x; 1.2623x over previous
#include <cuda_runtime.h>
#include <cuda_fp16.h>
#include <cstdint>
#include <cstddef>

// ---------------- problem constants ----------------
#define B_    32
#define NTOK  3136
#define C_    512
#define NH    8
#define S_    49
#define G_    64
#define M_    (B_*G_*S_)    // 100352 (784*128)
#define QKVN  1536
#define SCALE_ 0.125f
#define L2T_OVER16 0.8304820237218406f

// ---------------- scratch ----------------
__device__ float g_qkv[(size_t)M_ * QKVN];       // fp32 qkv (roped), (b,g,s) rows
__device__ __half g_xhi[(size_t)M_ * C_];        // gathered x, split fp16
__device__ __half g_xlo[(size_t)M_ * C_];
__device__ __half g_wh[QKVN * C_];               // w_qkv, single fp16
__device__ __half g_ph[C_ * C_];                 // w_proj, single fp16
__device__ __half g_ahi[(size_t)M_ * C_];        // attention out, split fp16, (b,n) rows
__device__ __half g_alo[(size_t)M_ * C_];

// row r (in b,g,s order) -> x row offset (b,n)
__device__ __forceinline__ size_t gather_row_off(int r) {
    int b   = r / (G_ * S_);
    int rem = r - b * (G_ * S_);
    int g   = rem / S_;
    int s   = rem - g * S_;
    int sy  = s / 7;
    int sx  = s - sy * 7;
    int n   = ((g >> 3) * 7 + sy) * 56 + (g & 7) * 7 + sx;
    return ((size_t)b * NTOK + n) * C_;
}

// ---------------- asm wrappers ----------------
__device__ __forceinline__ uint32_t smem_u32(const void* p) {
    uint32_t a;
    asm("{ .reg .u64 t; cvta.to.shared.u64 t, %1; cvt.u32.u64 %0, t; }" : "=r"(a) : "l"(p));
    return a;
}
__device__ __forceinline__ void cp16(uint32_t saddr, const void* g) {
    asm volatile("cp.async.cg.shared.global [%0], [%1], 16;" :: "r"(saddr), "l"(g));
}
__device__ __forceinline__ void cp_commit() {
    asm volatile("cp.async.commit_group;" ::: "memory");
}
__device__ __forceinline__ void cp_wait0() {
    asm volatile("cp.async.wait_group 0;" ::: "memory");
}
__device__ __forceinline__ void cp_wait1() {
    asm volatile("cp.async.wait_group 1;" ::: "memory");
}
__device__ __forceinline__ void ldm4(uint32_t* r, uint32_t addr) {
    asm volatile("ldmatrix.sync.aligned.m8n8.x4.shared.b16 {%0,%1,%2,%3}, [%4];"
        : "=r"(r[0]), "=r"(r[1]), "=r"(r[2]), "=r"(r[3]) : "r"(addr));
}
__device__ __forceinline__ void mma16816(float* c, const uint32_t* a, const uint32_t* b) {
    asm volatile("mma.sync.aligned.m16n8k16.row.col.f32.f16.f16.f32 "
        "{%0,%1,%2,%3}, {%4,%5,%6,%7}, {%8,%9}, {%0,%1,%2,%3};"
        : "+f"(c[0]), "+f"(c[1]), "+f"(c[2]), "+f"(c[3])
        : "r"(a[0]), "r"(a[1]), "r"(a[2]), "r"(a[3]), "r"(b[0]), "r"(b[1]));
}

// ---------------- conversion kernels ----------------
__global__ __launch_bounds__(256) void conv_x_kernel(const float* __restrict__ x) {
    int idx = blockIdx.x * 256 + threadIdx.x;       // M_*128 threads
    int r = idx >> 7;
    int q = (idx & 127) << 2;
    float4 v = *(const float4*)(x + gather_row_off(r) + q);
    float vv[4] = {v.x, v.y, v.z, v.w};
    uint32_t hp[2], lp[2];
    #pragma unroll
    for (int p = 0; p < 2; p++) {
        __half2 h2, l2;
        h2.x = __float2half_rn(vv[2*p]);
        h2.y = __float2half_rn(vv[2*p+1]);
        l2.x = __float2half_rn(vv[2*p]   - __half2float(h2.x));
        l2.y = __float2half_rn(vv[2*p+1] - __half2float(h2.y));
        hp[p] = *(uint32_t*)&h2;
        lp[p] = *(uint32_t*)&l2;
    }
    size_t o = (size_t)r * C_ + q;
    *(uint2*)(g_xhi + o) = make_uint2(hp[0], hp[1]);
    *(uint2*)(g_xlo + o) = make_uint2(lp[0], lp[1]);
}

__global__ __launch_bounds__(256) void conv_w_kernel(const float* __restrict__ w,
                                                     __half* __restrict__ h) {
    int idx = blockIdx.x * 256 + threadIdx.x;
    size_t o = (size_t)idx << 2;
    float4 v = *(const float4*)(w + o);
    __half2 a, b;
    a.x = __float2half_rn(v.x); a.y = __float2half_rn(v.y);
    b.x = __float2half_rn(v.z); b.y = __float2half_rn(v.w);
    *(uint2*)(h + o) = make_uint2(*(uint32_t*)&a, *(uint32_t*)&b);
}

// ---------------- split-fp16 HMMA GEMM (2-term) ----------------
// C[r][d] = sum_k (Ahi+Alo)[r][k]*B[d][k] (+bias / +rope), K=512
// block 128x128, 8 warps (2x4), warp tile 64x32, BK=32, 3-stage cp.async
// Tiles row-paired: 2 logical rows (64B) per 128B physical row, SW128 xor swizzle.
// smem per stage: Ahi(8K) Alo(8K) B(8K) = 24KB
#define STG_BYTES 24576u
#define NSTG 3
#define DYN_SMEM (NSTG * STG_BYTES)

template <int NCOLS, bool BIAS, bool ROPE>
__global__ __launch_bounds__(256, 2) void mma_gemm(
    const __half* __restrict__ Ahi, const __half* __restrict__ Alo,
    const __half* __restrict__ Bm,
    const float* __restrict__ bias, float* __restrict__ Cc)
{
    extern __shared__ __align__(1024) char dyn[];
    const uint32_t sbase = smem_u32(dyn);

    const int tid  = threadIdx.x;
    const int lane = tid & 31;
    const int wid  = tid >> 5;
    const int wm   = wid >> 2;          // 0..1
    const int wn   = wid & 3;           // 0..3
    const int bm   = blockIdx.y * 128;
    const int bn   = blockIdx.x * 128;

    // ---- loader: 3 groups of 64 threads (grp 3 idle); 1 phys row/thread ----
    const int grp  = tid >> 6;          // 0:Ahi 1:Alo 2:B 3:idle
    const int prow = tid & 63;
    const __half* gsrc;
    if      (grp == 0) gsrc = Ahi + (size_t)bm * C_;
    else if (grp == 1) gsrc = Alo + (size_t)bm * C_;
    else               gsrc = Bm  + (size_t)bn * C_;
    const __half* grow = gsrc + (size_t)(2 * prow) * C_;
    const uint32_t smat = sbase + grp * 8192u + prow * 128u;
    const int sx = prow & 7;

    auto load_stage = [&](int st, int kc) {
        if (grp < 3) {
            const char* g0 = (const char*)(grow + kc * 32);
            uint32_t rb = smat + (uint32_t)st * STG_BYTES;
            #pragma unroll
            for (int c = 0; c < 8; c++)
                cp16(rb + (uint32_t)((c ^ sx) << 4), g0 + (c >> 2) * (C_ * 2) + (c & 3) * 16);
        }
    };

    // ---- fragment smem offsets (stage-relative), precomputed per ks ----
    const int a_r  = wm * 64 + (lane & 15);
    const int a_cp = lane >> 4;
    const int b_r0 = wn * 32 + (lane & 7) + ((lane & 16) >> 1);
    const int b_cp = (lane >> 3) & 1;

    uint32_t aoff[2][4], boff[2][2];
    #pragma unroll
    for (int ks = 0; ks < 2; ks++) {
        #pragma unroll
        for (int i = 0; i < 4; i++) {
            int r  = a_r + i * 16;
            int pr = r >> 1;
            int pc = ((r & 1) << 2) + 2 * ks + a_cp;
            aoff[ks][i] = (uint32_t)(pr * 128 + ((pc ^ (pr & 7)) << 4));
        }
        #pragma unroll
        for (int jj = 0; jj < 2; jj++) {
            int r  = b_r0 + jj * 16;
            int pr = r >> 1;
            int pc = ((r & 1) << 2) + 2 * ks + b_cp;
            boff[ks][jj] = 16384u + (uint32_t)(pr * 128 + ((pc ^ (pr & 7)) << 4));
        }
    }

    float acc[4][4][4];
    #pragma unroll
    for (int i = 0; i < 4; i++)
        #pragma unroll
        for (int j = 0; j < 4; j++)
            #pragma unroll
            for (int p = 0; p < 4; p++) acc[i][j][p] = 0.0f;

    load_stage(0, 0); cp_commit();
    load_stage(1, 1); cp_commit();

    uint32_t ah[2][4][4], al[2][4][4], bf[2][2][4];

    auto load_frags = [&](int buf, uint32_t base, int ks) {
        #pragma unroll
        for (int i = 0; i < 4; i++) {
            uint32_t ad = base + aoff[ks][i];
            ldm4(ah[buf][i], ad);
            ldm4(al[buf][i], ad + 8192u);
        }
        #pragma unroll
        for (int jj = 0; jj < 2; jj++)
            ldm4(bf[buf][jj], base + boff[ks][jj]);
    };
    auto do_mmas = [&](int buf) {
        #pragma unroll
        for (int i = 0; i < 4; i++)
            #pragma unroll
            for (int j = 0; j < 4; j++) {
                const uint32_t* bp = &bf[buf][j >> 1][(j & 1) * 2];
                mma16816(acc[i][j], ah[buf][i], bp);
                mma16816(acc[i][j], al[buf][i], bp);
            }
    };

    #pragma unroll 1
    for (int kc = 0; kc < 16; kc++) {
        if (kc < 15) cp_wait1(); else cp_wait0();
        __syncthreads();
        if (kc + 2 < 16) { load_stage((kc + 2) % NSTG, kc + 2); cp_commit(); }

        const uint32_t base = sbase + (uint32_t)(kc % NSTG) * STG_BYTES;
        load_frags(0, base, 0);
        load_frags(1, base, 1);
        do_mmas(0);
        do_mmas(1);
    }

    // ---- epilogue (optionally fused 2D RoPE) ----
    const int orow = bm + wm * 64 + (lane >> 2);
    const int ocol = bn + wn * 32 + (lane & 3) * 2;
    float bvx[4], bvy[4];
    if (BIAS) {
        #pragma unroll
        for (int j = 0; j < 4; j++) { bvx[j] = bias[ocol + j * 8]; bvy[j] = bias[ocol + j * 8 + 1]; }
    }
    #pragma unroll
    for (int i = 0; i < 4; i++) {
        const int rA = orow + i * 16;
        const int rB = rA + 8;
        int sA = 0, sB = 0;
        if (ROPE) { sA = rA % S_; sB = rB % S_; }
        #pragma unroll
        for (int j = 0; j < 4; j++) {
            const int cc = ocol + j * 8;
            float v0 = acc[i][j][0], v1 = acc[i][j][1];
            float v2 = acc[i][j][2], v3 = acc[i][j][3];
            if (ROPE && cc < 1024) {
                int m = (cc & 63) >> 1;
                float freq = exp2f(-(float)(m >> 1) * L2T_OVER16);
                float pA = (m & 1) ? (float)(sA / 7) : (float)(sA % 7);
                float pB = (m & 1) ? (float)(sB / 7) : (float)(sB % 7);
                float snA, csA, snB, csB;
                sincosf(pA * freq, &snA, &csA);
                sincosf(pB * freq, &snB, &csB);
                float t0 = v0 * csA - v1 * snA, t1 = v0 * snA + v1 * csA;
                float t2 = v2 * csB - v3 * snB, t3 = v2 * snB + v3 * csB;
                v0 = t0; v1 = t1; v2 = t2; v3 = t3;
            }
            if (BIAS) { v0 += bvx[j]; v1 += bvy[j]; v2 += bvx[j]; v3 += bvy[j]; }
            *(float2*)(Cc + (size_t)rA * NCOLS + cc) = make_float2(v0, v1);
            *(float2*)(Cc + (size_t)rB * NCOLS + cc) = make_float2(v2, v3);
        }
    }
}

// ---------------- windowed attention (writes split fp16) ----------------
__global__ __launch_bounds__(256) void attn_kernel() {
    __shared__ float qs[49 * 68];
    __shared__ float ks[49 * 68];
    __shared__ float vs[49 * 64];
    __shared__ float sc[49 * 49];

    const int tid = threadIdx.x;
    const int h   = blockIdx.x & 7;
    const int bg  = blockIdx.x >> 3;

    const size_t base = (size_t)bg * S_ * QKVN + h * 64;

    for (int i = tid; i < 49 * 16; i += 256) {
        int s  = i >> 4;
        int d4 = (i & 15) * 4;
        size_t ro = base + (size_t)s * QKVN + d4;
        float4 q = *(const float4*)(g_qkv + ro);
        float4 k = *(const float4*)(g_qkv + ro + 512);
        float4 v = *(const float4*)(g_qkv + ro + 1024);
        *(float4*)&qs[s * 68 + d4] = q;
        *(float4*)&ks[s * 68 + d4] = k;
        *(float4*)&vs[s * 64 + d4] = v;
    }
    __syncthreads();

    for (int p = tid; p < 49 * 49; p += 256) {
        int s  = p / 49;
        int tt = p - s * 49;
        const float* qp = &qs[s * 68];
        const float* kp = &ks[tt * 68];
        float acc = 0.0f;
        #pragma unroll
        for (int d = 0; d < 64; d += 4) {
            float4 a = *(const float4*)(qp + d);
            float4 b = *(const float4*)(kp + d);
            acc += a.x * b.x + a.y * b.y + a.z * b.z + a.w * b.w;
        }
        sc[p] = acc * SCALE_;
    }
    __syncthreads();

    const int warp = tid >> 5, lane = tid & 31;
    for (int row = warp; row < 49; row += 8) {
        float mx = -1e30f;
        for (int t = lane; t < 49; t += 32) mx = fmaxf(mx, sc[row * 49 + t]);
        #pragma unroll
        for (int o = 16; o > 0; o >>= 1) mx = fmaxf(mx, __shfl_xor_sync(0xffffffffu, mx, o));
        float sum = 0.0f;
        for (int t = lane; t < 49; t += 32) {
            float e = __expf(sc[row * 49 + t] - mx);
            sc[row * 49 + t] = e;
            sum += e;
        }
        #pragma unroll
        for (int o = 16; o > 0; o >>= 1) sum += __shfl_xor_sync(0xffffffffu, sum, o);
        float inv = 1.0f / sum;
        for (int t = lane; t < 49; t += 32) sc[row * 49 + t] *= inv;
    }
    __syncthreads();

    const int g = bg & 63;
    const int b = bg >> 6;
    for (int o = tid; o < 49 * 64; o += 256) {
        int s = o >> 6;
        int d = o & 63;
        const float* sr = &sc[s * 49];
        float acc = 0.0f;
        #pragma unroll
        for (int tt = 0; tt < 49; tt++)
            acc = fmaf(sr[tt], vs[tt * 64 + d], acc);
        int sy = s / 7, sx = s - sy * 7;
        int n  = ((g >> 3) * 7 + sy) * 56 + (g & 7) * 7 + sx;
        size_t off = ((size_t)(b * NTOK + n)) * C_ + h * 64 + d;
        __half hv = __float2half_rn(acc);
        g_ahi[off] = hv;
        g_alo[off] = __float2half_rn(acc - __half2float(hv));
    }
}

// ---------------- launch ----------------
extern "C" void kernel_launch(void* const* d_in, const int* in_sizes, int n_in,
                              void* d_out, int out_size)
{
    const float* x      = (const float*)d_in[0];
    const float* w_qkv  = (const float*)d_in[1];
    const float* w_proj = (const float*)d_in[2];
    const float* b_proj = (const float*)d_in[3];
    float* out = (float*)d_out;

    void *qkvp, *xhip, *xlop, *whp, *php, *ahip, *alop;
    cudaGetSymbolAddress(&qkvp, g_qkv);
    cudaGetSymbolAddress(&xhip, g_xhi); cudaGetSymbolAddress(&xlop, g_xlo);
    cudaGetSymbolAddress(&whp, g_wh);   cudaGetSymbolAddress(&php, g_ph);
    cudaGetSymbolAddress(&ahip, g_ahi); cudaGetSymbolAddress(&alop, g_alo);

    cudaFuncSetAttribute(mma_gemm<QKVN, false, true>,
                         cudaFuncAttributeMaxDynamicSharedMemorySize, DYN_SMEM);
    cudaFuncSetAttribute(mma_gemm<C_, true, false>,
                         cudaFuncAttributeMaxDynamicSharedMemorySize, DYN_SMEM);

    // 0) conversions
    conv_x_kernel<<<M_ * 128 / 256, 256>>>(x);
    conv_w_kernel<<<QKVN * C_ / 4 / 256, 256>>>(w_qkv, (__half*)whp);
    conv_w_kernel<<<C_ * C_ / 4 / 256, 256>>>(w_proj, (__half*)php);

    // 1) QKV GEMM (2-term split-fp16 HMMA) with fused RoPE in epilogue
    dim3 g1(QKVN / 128, M_ / 128);
    mma_gemm<QKVN, false, true><<<g1, 256, DYN_SMEM>>>(
        (const __half*)xhip, (const __half*)xlop, (const __half*)whp,
        nullptr, (float*)qkvp);

    // 2) windowed attention
    attn_kernel<<<B_ * G_ * NH, 256>>>();

    // 3) projection GEMM + bias
    dim3 g2(C_ / 128, M_ / 128);
    mma_gemm<C_, true, false><<<g2, 256, DYN_SMEM>>>(
        (const __half*)ahip, (const __half*)alop, (const __half*)php,
        b_proj, out);
}

// round 8
// speedup vs baseline: 2.8907x; 1.3751x over previous
#include <cuda_runtime.h>
#include <cuda_fp16.h>
#include <cstdint>
#include <cstddef>

// ---------------- problem constants ----------------
#define B_    32
#define NTOK  3136
#define C_    512
#define NH    8
#define S_    49
#define G_    64
#define M_    (B_*G_*S_)    // 100352 (784*128)
#define QKVN  1536
#define SCALE_ 0.125f
#define L2T_OVER16 0.8304820237218406f

// ---------------- scratch ----------------
__device__ float g_qkv[(size_t)M_ * QKVN];       // fp32 qkv (roped), (b,g,s) rows
__device__ __half g_xhi[(size_t)M_ * C_];        // gathered x, split fp16
__device__ __half g_xlo[(size_t)M_ * C_];
__device__ __half g_wh[QKVN * C_];               // w_qkv, single fp16
__device__ __half g_ph[C_ * C_];                 // w_proj, single fp16
__device__ __half g_ahi[(size_t)M_ * C_];        // attention out, split fp16, (b,n) rows
__device__ __half g_alo[(size_t)M_ * C_];

// row r (in b,g,s order) -> x row offset (b,n)
__device__ __forceinline__ size_t gather_row_off(int r) {
    int b   = r / (G_ * S_);
    int rem = r - b * (G_ * S_);
    int g   = rem / S_;
    int s   = rem - g * S_;
    int sy  = s / 7;
    int sx  = s - sy * 7;
    int n   = ((g >> 3) * 7 + sy) * 56 + (g & 7) * 7 + sx;
    return ((size_t)b * NTOK + n) * C_;
}

// ---------------- asm wrappers ----------------
__device__ __forceinline__ uint32_t smem_u32(const void* p) {
    uint32_t a;
    asm("{ .reg .u64 t; cvta.to.shared.u64 t, %1; cvt.u32.u64 %0, t; }" : "=r"(a) : "l"(p));
    return a;
}
__device__ __forceinline__ void cp16(uint32_t saddr, const void* g) {
    asm volatile("cp.async.cg.shared.global [%0], [%1], 16;" :: "r"(saddr), "l"(g));
}
__device__ __forceinline__ void cp_commit() {
    asm volatile("cp.async.commit_group;" ::: "memory");
}
__device__ __forceinline__ void cp_wait0() {
    asm volatile("cp.async.wait_group 0;" ::: "memory");
}
__device__ __forceinline__ void cp_wait1() {
    asm volatile("cp.async.wait_group 1;" ::: "memory");
}
__device__ __forceinline__ void ldm4(uint32_t* r, uint32_t addr) {
    asm volatile("ldmatrix.sync.aligned.m8n8.x4.shared.b16 {%0,%1,%2,%3}, [%4];"
        : "=r"(r[0]), "=r"(r[1]), "=r"(r[2]), "=r"(r[3]) : "r"(addr));
}
__device__ __forceinline__ void ldm4t(uint32_t* r, uint32_t addr) {
    asm volatile("ldmatrix.sync.aligned.m8n8.x4.trans.shared.b16 {%0,%1,%2,%3}, [%4];"
        : "=r"(r[0]), "=r"(r[1]), "=r"(r[2]), "=r"(r[3]) : "r"(addr));
}
__device__ __forceinline__ void mma16816(float* c, const uint32_t* a, const uint32_t* b) {
    asm volatile("mma.sync.aligned.m16n8k16.row.col.f32.f16.f16.f32 "
        "{%0,%1,%2,%3}, {%4,%5,%6,%7}, {%8,%9}, {%0,%1,%2,%3};"
        : "+f"(c[0]), "+f"(c[1]), "+f"(c[2]), "+f"(c[3])
        : "r"(a[0]), "r"(a[1]), "r"(a[2]), "r"(a[3]), "r"(b[0]), "r"(b[1]));
}

// ---------------- conversion kernels ----------------
__global__ __launch_bounds__(256) void conv_x_kernel(const float* __restrict__ x) {
    int idx = blockIdx.x * 256 + threadIdx.x;       // M_*128 threads
    int r = idx >> 7;
    int q = (idx & 127) << 2;
    float4 v = *(const float4*)(x + gather_row_off(r) + q);
    float vv[4] = {v.x, v.y, v.z, v.w};
    uint32_t hp[2], lp[2];
    #pragma unroll
    for (int p = 0; p < 2; p++) {
        __half2 h2, l2;
        h2.x = __float2half_rn(vv[2*p]);
        h2.y = __float2half_rn(vv[2*p+1]);
        l2.x = __float2half_rn(vv[2*p]   - __half2float(h2.x));
        l2.y = __float2half_rn(vv[2*p+1] - __half2float(h2.y));
        hp[p] = *(uint32_t*)&h2;
        lp[p] = *(uint32_t*)&l2;
    }
    size_t o = (size_t)r * C_ + q;
    *(uint2*)(g_xhi + o) = make_uint2(hp[0], hp[1]);
    *(uint2*)(g_xlo + o) = make_uint2(lp[0], lp[1]);
}

__global__ __launch_bounds__(256) void conv_w_kernel(const float* __restrict__ w,
                                                     __half* __restrict__ h) {
    int idx = blockIdx.x * 256 + threadIdx.x;
    size_t o = (size_t)idx << 2;
    float4 v = *(const float4*)(w + o);
    __half2 a, b;
    a.x = __float2half_rn(v.x); a.y = __float2half_rn(v.y);
    b.x = __float2half_rn(v.z); b.y = __float2half_rn(v.w);
    *(uint2*)(h + o) = make_uint2(*(uint32_t*)&a, *(uint32_t*)&b);
}

// ---------------- split-fp16 HMMA GEMM (2-term) ----------------
#define STG_BYTES 24576u
#define NSTG 3
#define DYN_SMEM (NSTG * STG_BYTES)

template <int NCOLS, bool BIAS, bool ROPE>
__global__ __launch_bounds__(256, 2) void mma_gemm(
    const __half* __restrict__ Ahi, const __half* __restrict__ Alo,
    const __half* __restrict__ Bm,
    const float* __restrict__ bias, float* __restrict__ Cc)
{
    extern __shared__ __align__(1024) char dyn[];
    const uint32_t sbase = smem_u32(dyn);

    const int tid  = threadIdx.x;
    const int lane = tid & 31;
    const int wid  = tid >> 5;
    const int wm   = wid >> 2;
    const int wn   = wid & 3;
    const int bm   = blockIdx.y * 128;
    const int bn   = blockIdx.x * 128;

    const int grp  = tid >> 6;          // 0:Ahi 1:Alo 2:B 3:idle
    const int prow = tid & 63;
    const __half* gsrc;
    if      (grp == 0) gsrc = Ahi + (size_t)bm * C_;
    else if (grp == 1) gsrc = Alo + (size_t)bm * C_;
    else               gsrc = Bm  + (size_t)bn * C_;
    const __half* grow = gsrc + (size_t)(2 * prow) * C_;
    const uint32_t smat = sbase + grp * 8192u + prow * 128u;
    const int sx = prow & 7;

    auto load_stage = [&](int st, int kc) {
        if (grp < 3) {
            const char* g0 = (const char*)(grow + kc * 32);
            uint32_t rb = smat + (uint32_t)st * STG_BYTES;
            #pragma unroll
            for (int c = 0; c < 8; c++)
                cp16(rb + (uint32_t)((c ^ sx) << 4), g0 + (c >> 2) * (C_ * 2) + (c & 3) * 16);
        }
    };

    const int a_r  = wm * 64 + (lane & 15);
    const int a_cp = lane >> 4;
    const int b_r0 = wn * 32 + (lane & 7) + ((lane & 16) >> 1);
    const int b_cp = (lane >> 3) & 1;

    uint32_t aoff[2][4], boff[2][2];
    #pragma unroll
    for (int ks = 0; ks < 2; ks++) {
        #pragma unroll
        for (int i = 0; i < 4; i++) {
            int r  = a_r + i * 16;
            int pr = r >> 1;
            int pc = ((r & 1) << 2) + 2 * ks + a_cp;
            aoff[ks][i] = (uint32_t)(pr * 128 + ((pc ^ (pr & 7)) << 4));
        }
        #pragma unroll
        for (int jj = 0; jj < 2; jj++) {
            int r  = b_r0 + jj * 16;
            int pr = r >> 1;
            int pc = ((r & 1) << 2) + 2 * ks + b_cp;
            boff[ks][jj] = 16384u + (uint32_t)(pr * 128 + ((pc ^ (pr & 7)) << 4));
        }
    }

    float acc[4][4][4];
    #pragma unroll
    for (int i = 0; i < 4; i++)
        #pragma unroll
        for (int j = 0; j < 4; j++)
            #pragma unroll
            for (int p = 0; p < 4; p++) acc[i][j][p] = 0.0f;

    load_stage(0, 0); cp_commit();
    load_stage(1, 1); cp_commit();

    uint32_t ah[2][4][4], al[2][4][4], bf[2][2][4];

    auto load_frags = [&](int buf, uint32_t base, int ks) {
        #pragma unroll
        for (int i = 0; i < 4; i++) {
            uint32_t ad = base + aoff[ks][i];
            ldm4(ah[buf][i], ad);
            ldm4(al[buf][i], ad + 8192u);
        }
        #pragma unroll
        for (int jj = 0; jj < 2; jj++)
            ldm4(bf[buf][jj], base + boff[ks][jj]);
    };
    auto do_mmas = [&](int buf) {
        #pragma unroll
        for (int i = 0; i < 4; i++)
            #pragma unroll
            for (int j = 0; j < 4; j++) {
                const uint32_t* bp = &bf[buf][j >> 1][(j & 1) * 2];
                mma16816(acc[i][j], ah[buf][i], bp);
                mma16816(acc[i][j], al[buf][i], bp);
            }
    };

    #pragma unroll 1
    for (int kc = 0; kc < 16; kc++) {
        if (kc < 15) cp_wait1(); else cp_wait0();
        __syncthreads();
        if (kc + 2 < 16) { load_stage((kc + 2) % NSTG, kc + 2); cp_commit(); }

        const uint32_t base = sbase + (uint32_t)(kc % NSTG) * STG_BYTES;
        load_frags(0, base, 0);
        load_frags(1, base, 1);
        do_mmas(0);
        do_mmas(1);
    }

    const int orow = bm + wm * 64 + (lane >> 2);
    const int ocol = bn + wn * 32 + (lane & 3) * 2;
    float bvx[4], bvy[4];
    if (BIAS) {
        #pragma unroll
        for (int j = 0; j < 4; j++) { bvx[j] = bias[ocol + j * 8]; bvy[j] = bias[ocol + j * 8 + 1]; }
    }
    #pragma unroll
    for (int i = 0; i < 4; i++) {
        const int rA = orow + i * 16;
        const int rB = rA + 8;
        int sA = 0, sB = 0;
        if (ROPE) { sA = rA % S_; sB = rB % S_; }
        #pragma unroll
        for (int j = 0; j < 4; j++) {
            const int cc = ocol + j * 8;
            float v0 = acc[i][j][0], v1 = acc[i][j][1];
            float v2 = acc[i][j][2], v3 = acc[i][j][3];
            if (ROPE && cc < 1024) {
                int m = (cc & 63) >> 1;
                float freq = exp2f(-(float)(m >> 1) * L2T_OVER16);
                float pA = (m & 1) ? (float)(sA / 7) : (float)(sA % 7);
                float pB = (m & 1) ? (float)(sB / 7) : (float)(sB % 7);
                float snA, csA, snB, csB;
                sincosf(pA * freq, &snA, &csA);
                sincosf(pB * freq, &snB, &csB);
                float t0 = v0 * csA - v1 * snA, t1 = v0 * snA + v1 * csA;
                float t2 = v2 * csB - v3 * snB, t3 = v2 * snB + v3 * csB;
                v0 = t0; v1 = t1; v2 = t2; v3 = t3;
            }
            if (BIAS) { v0 += bvx[j]; v1 += bvy[j]; v2 += bvx[j]; v3 += bvy[j]; }
            *(float2*)(Cc + (size_t)rA * NCOLS + cc) = make_float2(v0, v1);
            *(float2*)(Cc + (size_t)rB * NCOLS + cc) = make_float2(v2, v3);
        }
    }
}

// ---------------- tensor-core windowed attention ----------------
// one block per (b,g,h), 128 threads / 4 warps; S=49 padded to 64.
// smem tiles (64 rows x 128B, SW128-style xor swizzle):
//  QHI 0, QLO 8192, KK 16384, VHI 24576, VLO 32768
#define T_QHI 0u
#define T_QLO 8192u
#define T_KK  16384u
#define T_VHI 24576u
#define T_VLO 32768u

__global__ __launch_bounds__(128) void attn_tc_kernel() {
    __shared__ __align__(1024) char sm[40960];
    const uint32_t sb = smem_u32(sm);

    const int tid  = threadIdx.x;
    const int lane = tid & 31;
    const int w    = tid >> 5;
    const int h    = blockIdx.x & 7;
    const int bg   = blockIdx.x >> 3;
    const size_t base = (size_t)bg * S_ * QKVN + h * 64;

    // zero-fill all tiles (padding rows must be 0)
    #pragma unroll
    for (int i = tid; i < 40960 / 16; i += 128)
        ((uint4*)sm)[i] = make_uint4(0, 0, 0, 0);
    __syncthreads();

    // fill rows 0..48: q -> hi/lo, k -> single, v -> hi/lo
    for (int i = tid; i < S_ * 16; i += 128) {
        int s   = i >> 4;
        int seg = i & 15;                 // 4-float segment
        size_t ro = base + (size_t)s * QKVN + seg * 4;
        float4 q = *(const float4*)(g_qkv + ro);
        float4 k = *(const float4*)(g_qkv + ro + 512);
        float4 v = *(const float4*)(g_qkv + ro + 1024);
        int chunk = seg >> 1;
        uint32_t addr = (uint32_t)(s * 128 + ((chunk ^ (s & 7)) << 4) + (seg & 1) * 8);

        __half2 qh0, qh1, ql0, ql1;
        qh0.x = __float2half_rn(q.x); qh0.y = __float2half_rn(q.y);
        qh1.x = __float2half_rn(q.z); qh1.y = __float2half_rn(q.w);
        ql0.x = __float2half_rn(q.x - __half2float(qh0.x));
        ql0.y = __float2half_rn(q.y - __half2float(qh0.y));
        ql1.x = __float2half_rn(q.z - __half2float(qh1.x));
        ql1.y = __float2half_rn(q.w - __half2float(qh1.y));
        *(uint2*)(sm + T_QHI + addr) = make_uint2(*(uint32_t*)&qh0, *(uint32_t*)&qh1);
        *(uint2*)(sm + T_QLO + addr) = make_uint2(*(uint32_t*)&ql0, *(uint32_t*)&ql1);

        __half2 kh0, kh1;
        kh0.x = __float2half_rn(k.x); kh0.y = __float2half_rn(k.y);
        kh1.x = __float2half_rn(k.z); kh1.y = __float2half_rn(k.w);
        *(uint2*)(sm + T_KK + addr) = make_uint2(*(uint32_t*)&kh0, *(uint32_t*)&kh1);

        __half2 vh0, vh1, vl0, vl1;
        vh0.x = __float2half_rn(v.x); vh0.y = __float2half_rn(v.y);
        vh1.x = __float2half_rn(v.z); vh1.y = __float2half_rn(v.w);
        vl0.x = __float2half_rn(v.x - __half2float(vh0.x));
        vl0.y = __float2half_rn(v.y - __half2float(vh0.y));
        vl1.x = __float2half_rn(v.z - __half2float(vh1.x));
        vl1.y = __float2half_rn(v.w - __half2float(vh1.y));
        *(uint2*)(sm + T_VHI + addr) = make_uint2(*(uint32_t*)&vh0, *(uint32_t*)&vh1);
        *(uint2*)(sm + T_VLO + addr) = make_uint2(*(uint32_t*)&vl0, *(uint32_t*)&vl1);
    }
    __syncthreads();

    // ---- QK^T: warp w computes score rows w*16..w*16+15, cols t 0..63 ----
    const int a_r  = w * 16 + (lane & 15);
    const int a_cp = lane >> 4;
    const int b_r0 = (lane & 7) + ((lane & 16) >> 1);
    const int b_cp = (lane >> 3) & 1;

    float sc[8][4];
    #pragma unroll
    for (int j = 0; j < 8; j++)
        #pragma unroll
        for (int p = 0; p < 4; p++) sc[j][p] = 0.0f;

    #pragma unroll
    for (int ks = 0; ks < 4; ks++) {
        uint32_t ahq[4], alq[4], bk[4][4];
        {
            int ch = 2 * ks + a_cp;
            uint32_t ad = sb + (uint32_t)(a_r * 128 + ((ch ^ (a_r & 7)) << 4));
            ldm4(ahq, ad + T_QHI);
            ldm4(alq, ad + T_QLO);
        }
        #pragma unroll
        for (int jn = 0; jn < 4; jn++) {
            int r  = jn * 16 + b_r0;
            int ch = 2 * ks + b_cp;
            ldm4(bk[jn], sb + T_KK + (uint32_t)(r * 128 + ((ch ^ (r & 7)) << 4)));
        }
        #pragma unroll
        for (int j = 0; j < 8; j++) {
            const uint32_t* bp = &bk[j >> 1][(j & 1) * 2];
            mma16816(sc[j], ahq, bp);
            mma16816(sc[j], alq, bp);
        }
    }

    // ---- register softmax (rows r0 = w*16 + lane>>2, r1 = r0+8) ----
    #pragma unroll
    for (int j = 0; j < 8; j++) {
        int t0 = j * 8 + 2 * (lane & 3);
        sc[j][0] = (t0     < S_) ? sc[j][0] * SCALE_ : -1e30f;
        sc[j][1] = (t0 + 1 < S_) ? sc[j][1] * SCALE_ : -1e30f;
        sc[j][2] = (t0     < S_) ? sc[j][2] * SCALE_ : -1e30f;
        sc[j][3] = (t0 + 1 < S_) ? sc[j][3] * SCALE_ : -1e30f;
    }
    float mx0 = -1e30f, mx1 = -1e30f;
    #pragma unroll
    for (int j = 0; j < 8; j++) {
        mx0 = fmaxf(mx0, fmaxf(sc[j][0], sc[j][1]));
        mx1 = fmaxf(mx1, fmaxf(sc[j][2], sc[j][3]));
    }
    mx0 = fmaxf(mx0, __shfl_xor_sync(0xffffffffu, mx0, 1));
    mx0 = fmaxf(mx0, __shfl_xor_sync(0xffffffffu, mx0, 2));
    mx1 = fmaxf(mx1, __shfl_xor_sync(0xffffffffu, mx1, 1));
    mx1 = fmaxf(mx1, __shfl_xor_sync(0xffffffffu, mx1, 2));
    float sum0 = 0.0f, sum1 = 0.0f;
    #pragma unroll
    for (int j = 0; j < 8; j++) {
        sc[j][0] = __expf(sc[j][0] - mx0);
        sc[j][1] = __expf(sc[j][1] - mx0);
        sc[j][2] = __expf(sc[j][2] - mx1);
        sc[j][3] = __expf(sc[j][3] - mx1);
        sum0 += sc[j][0] + sc[j][1];
        sum1 += sc[j][2] + sc[j][3];
    }
    sum0 += __shfl_xor_sync(0xffffffffu, sum0, 1);
    sum0 += __shfl_xor_sync(0xffffffffu, sum0, 2);
    sum1 += __shfl_xor_sync(0xffffffffu, sum1, 1);
    sum1 += __shfl_xor_sync(0xffffffffu, sum1, 2);

    // ---- pack P (unnormalized) as fp16 A fragments ----
    uint32_t pa[4][4];
    #pragma unroll
    for (int kt = 0; kt < 4; kt++) {
        __half2 t;
        t = __float22half2_rn(make_float2(sc[2*kt][0],   sc[2*kt][1]));   pa[kt][0] = *(uint32_t*)&t;
        t = __float22half2_rn(make_float2(sc[2*kt][2],   sc[2*kt][3]));   pa[kt][1] = *(uint32_t*)&t;
        t = __float22half2_rn(make_float2(sc[2*kt+1][0], sc[2*kt+1][1])); pa[kt][2] = *(uint32_t*)&t;
        t = __float22half2_rn(make_float2(sc[2*kt+1][2], sc[2*kt+1][3])); pa[kt][3] = *(uint32_t*)&t;
    }

    // ---- PV: out[s][d] = sum_t P[s][t] * (Vhi+Vlo)[t][d] ----
    float oacc[8][4];
    #pragma unroll
    for (int nb = 0; nb < 8; nb++)
        #pragma unroll
        for (int p = 0; p < 4; p++) oacc[nb][p] = 0.0f;

    #pragma unroll
    for (int kt = 0; kt < 4; kt++) {
        uint32_t bvh[4][4], bvl[4][4];
        #pragma unroll
        for (int ii = 0; ii < 4; ii++) {
            int rowk  = kt * 16 + ((lane >> 3) & 1) * 8 + (lane & 7);
            int chunk = 2 * ii + (lane >> 4);
            uint32_t ad = sb + (uint32_t)(rowk * 128 + ((chunk ^ (rowk & 7)) << 4));
            ldm4t(bvh[ii], ad + T_VHI);
            ldm4t(bvl[ii], ad + T_VLO);
        }
        #pragma unroll
        for (int nb = 0; nb < 8; nb++) {
            mma16816(oacc[nb], pa[kt], &bvh[nb >> 1][(nb & 1) * 2]);
            mma16816(oacc[nb], pa[kt], &bvl[nb >> 1][(nb & 1) * 2]);
        }
    }

    // ---- normalize + scatter to (b,n,c), split fp16 ----
    const float inv0 = 1.0f / sum0;
    const float inv1 = 1.0f / sum1;
    const int g = bg & 63;
    const int b = bg >> 6;
    const int s0 = w * 16 + (lane >> 2);
    const int s1 = s0 + 8;
    const int colb = 2 * (lane & 3);

    #pragma unroll
    for (int half = 0; half < 2; half++) {
        int s = half ? s1 : s0;
        if (s >= S_) continue;
        float inv = half ? inv1 : inv0;
        int sy = s / 7, sx = s - sy * 7;
        int n  = ((g >> 3) * 7 + sy) * 56 + (g & 7) * 7 + sx;
        size_t off = ((size_t)(b * NTOK + n)) * C_ + h * 64;
        #pragma unroll
        for (int nb = 0; nb < 8; nb++) {
            float o0 = oacc[nb][half * 2]     * inv;
            float o1 = oacc[nb][half * 2 + 1] * inv;
            __half2 hv, lv;
            hv.x = __float2half_rn(o0);
            hv.y = __float2half_rn(o1);
            lv.x = __float2half_rn(o0 - __half2float(hv.x));
            lv.y = __float2half_rn(o1 - __half2float(hv.y));
            size_t co = off + nb * 8 + colb;
            *(uint32_t*)(g_ahi + co) = *(uint32_t*)&hv;
            *(uint32_t*)(g_alo + co) = *(uint32_t*)&lv;
        }
    }
}

// ---------------- launch ----------------
extern "C" void kernel_launch(void* const* d_in, const int* in_sizes, int n_in,
                              void* d_out, int out_size)
{
    const float* x      = (const float*)d_in[0];
    const float* w_qkv  = (const float*)d_in[1];
    const float* w_proj = (const float*)d_in[2];
    const float* b_proj = (const float*)d_in[3];
    float* out = (float*)d_out;

    void *qkvp, *xhip, *xlop, *whp, *php, *ahip, *alop;
    cudaGetSymbolAddress(&qkvp, g_qkv);
    cudaGetSymbolAddress(&xhip, g_xhi); cudaGetSymbolAddress(&xlop, g_xlo);
    cudaGetSymbolAddress(&whp, g_wh);   cudaGetSymbolAddress(&php, g_ph);
    cudaGetSymbolAddress(&ahip, g_ahi); cudaGetSymbolAddress(&alop, g_alo);

    cudaFuncSetAttribute(mma_gemm<QKVN, false, true>,
                         cudaFuncAttributeMaxDynamicSharedMemorySize, DYN_SMEM);
    cudaFuncSetAttribute(mma_gemm<C_, true, false>,
                         cudaFuncAttributeMaxDynamicSharedMemorySize, DYN_SMEM);

    // 0) conversions
    conv_x_kernel<<<M_ * 128 / 256, 256>>>(x);
    conv_w_kernel<<<QKVN * C_ / 4 / 256, 256>>>(w_qkv, (__half*)whp);
    conv_w_kernel<<<C_ * C_ / 4 / 256, 256>>>(w_proj, (__half*)php);

    // 1) QKV GEMM (2-term split-fp16 HMMA) with fused RoPE in epilogue
    dim3 g1(QKVN / 128, M_ / 128);
    mma_gemm<QKVN, false, true><<<g1, 256, DYN_SMEM>>>(
        (const __half*)xhip, (const __half*)xlop, (const __half*)whp,
        nullptr, (float*)qkvp);

    // 2) tensor-core windowed attention
    attn_tc_kernel<<<B_ * G_ * NH, 128>>>();

    // 3) projection GEMM + bias
    dim3 g2(C_ / 128, M_ / 128);
    mma_gemm<C_, true, false><<<g2, 256, DYN_SMEM>>>(
        (const __half*)ahip, (const __half*)alop, (const __half*)php,
        b_proj, out);
}

// round 9
// speedup vs baseline: 3.7400x; 1.2938x over previous
#include <cuda_runtime.h>
#include <cuda_fp16.h>
#include <cstdint>
#include <cstddef>

// ---------------- problem constants ----------------
#define B_    32
#define NTOK  3136
#define C_    512
#define NH    8
#define S_    49
#define G_    64
#define M_    (B_*G_*S_)    // 100352 (784*128)
#define QKVN  1536
#define SCALE_ 0.125f
#define L2T_OVER16 0.8304820237218406f

// ---------------- scratch ----------------
__device__ float g_qkv[(size_t)M_ * QKVN];       // fp32 qkv (roped), (b,g,s) rows
__device__ __half g_xh[(size_t)M_ * C_];         // gathered x, single fp16
__device__ __half g_wh[QKVN * C_];               // w_qkv, single fp16
__device__ __half g_ph[C_ * C_];                 // w_proj, single fp16
__device__ __half g_ahi[(size_t)M_ * C_];        // attention out, split fp16, (b,n) rows
__device__ __half g_alo[(size_t)M_ * C_];

// row r (in b,g,s order) -> x row offset (b,n)
__device__ __forceinline__ size_t gather_row_off(int r) {
    int b   = r / (G_ * S_);
    int rem = r - b * (G_ * S_);
    int g   = rem / S_;
    int s   = rem - g * S_;
    int sy  = s / 7;
    int sx  = s - sy * 7;
    int n   = ((g >> 3) * 7 + sy) * 56 + (g & 7) * 7 + sx;
    return ((size_t)b * NTOK + n) * C_;
}

// ---------------- asm wrappers ----------------
__device__ __forceinline__ uint32_t smem_u32(const void* p) {
    uint32_t a;
    asm("{ .reg .u64 t; cvta.to.shared.u64 t, %1; cvt.u32.u64 %0, t; }" : "=r"(a) : "l"(p));
    return a;
}
__device__ __forceinline__ void cp16(uint32_t saddr, const void* g) {
    asm volatile("cp.async.cg.shared.global [%0], [%1], 16;" :: "r"(saddr), "l"(g));
}
__device__ __forceinline__ void cp_commit() {
    asm volatile("cp.async.commit_group;" ::: "memory");
}
__device__ __forceinline__ void cp_wait0() {
    asm volatile("cp.async.wait_group 0;" ::: "memory");
}
__device__ __forceinline__ void cp_wait1() {
    asm volatile("cp.async.wait_group 1;" ::: "memory");
}
__device__ __forceinline__ void ldm4(uint32_t* r, uint32_t addr) {
    asm volatile("ldmatrix.sync.aligned.m8n8.x4.shared.b16 {%0,%1,%2,%3}, [%4];"
        : "=r"(r[0]), "=r"(r[1]), "=r"(r[2]), "=r"(r[3]) : "r"(addr));
}
__device__ __forceinline__ void ldm4t(uint32_t* r, uint32_t addr) {
    asm volatile("ldmatrix.sync.aligned.m8n8.x4.trans.shared.b16 {%0,%1,%2,%3}, [%4];"
        : "=r"(r[0]), "=r"(r[1]), "=r"(r[2]), "=r"(r[3]) : "r"(addr));
}
__device__ __forceinline__ void mma16816(float* c, const uint32_t* a, const uint32_t* b) {
    asm volatile("mma.sync.aligned.m16n8k16.row.col.f32.f16.f16.f32 "
        "{%0,%1,%2,%3}, {%4,%5,%6,%7}, {%8,%9}, {%0,%1,%2,%3};"
        : "+f"(c[0]), "+f"(c[1]), "+f"(c[2]), "+f"(c[3])
        : "r"(a[0]), "r"(a[1]), "r"(a[2]), "r"(a[3]), "r"(b[0]), "r"(b[1]));
}

// ---------------- conversion kernels ----------------
__global__ __launch_bounds__(256) void conv_x_kernel(const float* __restrict__ x) {
    int idx = blockIdx.x * 256 + threadIdx.x;       // M_*128 threads
    int r = idx >> 7;
    int q = (idx & 127) << 2;
    float4 v = *(const float4*)(x + gather_row_off(r) + q);
    __half2 a, b;
    a.x = __float2half_rn(v.x); a.y = __float2half_rn(v.y);
    b.x = __float2half_rn(v.z); b.y = __float2half_rn(v.w);
    size_t o = (size_t)r * C_ + q;
    *(uint2*)(g_xh + o) = make_uint2(*(uint32_t*)&a, *(uint32_t*)&b);
}

__global__ __launch_bounds__(256) void conv_w_kernel(const float* __restrict__ w,
                                                     __half* __restrict__ h) {
    int idx = blockIdx.x * 256 + threadIdx.x;
    size_t o = (size_t)idx << 2;
    float4 v = *(const float4*)(w + o);
    __half2 a, b;
    a.x = __float2half_rn(v.x); a.y = __float2half_rn(v.y);
    b.x = __float2half_rn(v.z); b.y = __float2half_rn(v.w);
    *(uint2*)(h + o) = make_uint2(*(uint32_t*)&a, *(uint32_t*)&b);
}

// ---------------- split-fp16 HMMA GEMM (TERMS = 1 or 2 on A side) ----------------
// C[r][d] = sum_k A[r][k]*B[d][k] (+bias / +rope), K=512
// block 128x128, 8 warps (2x4), warp tile 64x32, BK=32, 3-stage cp.async
// smem per stage: A(8K) [Alo(8K) if TERMS=2 else unused] B(8K)
#define STG_BYTES 24576u
#define NSTG 3
#define DYN_SMEM (NSTG * STG_BYTES)

template <int NCOLS, bool BIAS, bool ROPE, int TERMS>
__global__ __launch_bounds__(256, 2) void mma_gemm(
    const __half* __restrict__ Ahi, const __half* __restrict__ Alo,
    const __half* __restrict__ Bm,
    const float* __restrict__ bias, float* __restrict__ Cc)
{
    extern __shared__ __align__(1024) char dyn[];
    const uint32_t sbase = smem_u32(dyn);

    const int tid  = threadIdx.x;
    const int lane = tid & 31;
    const int wid  = tid >> 5;
    const int wm   = wid >> 2;
    const int wn   = wid & 3;
    const int bm   = blockIdx.y * 128;
    const int bn   = blockIdx.x * 128;

    const int grp  = tid >> 6;          // 0:Ahi 1:Alo(if TERMS=2) 2:B 3:idle
    const int prow = tid & 63;
    const __half* gsrc = nullptr;
    if      (grp == 0)               gsrc = Ahi + (size_t)bm * C_;
    else if (grp == 1 && TERMS == 2) gsrc = Alo + (size_t)bm * C_;
    else if (grp == 2)               gsrc = Bm  + (size_t)bn * C_;
    const __half* grow = gsrc ? gsrc + (size_t)(2 * prow) * C_ : nullptr;
    const uint32_t smat = sbase + grp * 8192u + prow * 128u;
    const int sx = prow & 7;

    auto load_stage = [&](int st, int kc) {
        if (grow) {
            const char* g0 = (const char*)(grow + kc * 32);
            uint32_t rb = smat + (uint32_t)st * STG_BYTES;
            #pragma unroll
            for (int c = 0; c < 8; c++)
                cp16(rb + (uint32_t)((c ^ sx) << 4), g0 + (c >> 2) * (C_ * 2) + (c & 3) * 16);
        }
    };

    const int a_r  = wm * 64 + (lane & 15);
    const int a_cp = lane >> 4;
    const int b_r0 = wn * 32 + (lane & 7) + ((lane & 16) >> 1);
    const int b_cp = (lane >> 3) & 1;

    uint32_t aoff[2][4], boff[2][2];
    #pragma unroll
    for (int ks = 0; ks < 2; ks++) {
        #pragma unroll
        for (int i = 0; i < 4; i++) {
            int r  = a_r + i * 16;
            int pr = r >> 1;
            int pc = ((r & 1) << 2) + 2 * ks + a_cp;
            aoff[ks][i] = (uint32_t)(pr * 128 + ((pc ^ (pr & 7)) << 4));
        }
        #pragma unroll
        for (int jj = 0; jj < 2; jj++) {
            int r  = b_r0 + jj * 16;
            int pr = r >> 1;
            int pc = ((r & 1) << 2) + 2 * ks + b_cp;
            boff[ks][jj] = 16384u + (uint32_t)(pr * 128 + ((pc ^ (pr & 7)) << 4));
        }
    }

    float acc[4][4][4];
    #pragma unroll
    for (int i = 0; i < 4; i++)
        #pragma unroll
        for (int j = 0; j < 4; j++)
            #pragma unroll
            for (int p = 0; p < 4; p++) acc[i][j][p] = 0.0f;

    load_stage(0, 0); cp_commit();
    load_stage(1, 1); cp_commit();

    uint32_t ah[2][4][4], al[2][4][4], bf[2][2][4];

    auto load_frags = [&](int buf, uint32_t base, int ks) {
        #pragma unroll
        for (int i = 0; i < 4; i++) {
            uint32_t ad = base + aoff[ks][i];
            ldm4(ah[buf][i], ad);
            if (TERMS == 2) ldm4(al[buf][i], ad + 8192u);
        }
        #pragma unroll
        for (int jj = 0; jj < 2; jj++)
            ldm4(bf[buf][jj], base + boff[ks][jj]);
    };
    auto do_mmas = [&](int buf) {
        #pragma unroll
        for (int i = 0; i < 4; i++)
            #pragma unroll
            for (int j = 0; j < 4; j++) {
                const uint32_t* bp = &bf[buf][j >> 1][(j & 1) * 2];
                mma16816(acc[i][j], ah[buf][i], bp);
                if (TERMS == 2) mma16816(acc[i][j], al[buf][i], bp);
            }
    };

    #pragma unroll 1
    for (int kc = 0; kc < 16; kc++) {
        if (kc < 15) cp_wait1(); else cp_wait0();
        __syncthreads();
        if (kc + 2 < 16) { load_stage((kc + 2) % NSTG, kc + 2); cp_commit(); }

        const uint32_t base = sbase + (uint32_t)(kc % NSTG) * STG_BYTES;
        load_frags(0, base, 0);
        load_frags(1, base, 1);
        do_mmas(0);
        do_mmas(1);
    }

    const int orow = bm + wm * 64 + (lane >> 2);
    const int ocol = bn + wn * 32 + (lane & 3) * 2;
    float bvx[4], bvy[4];
    if (BIAS) {
        #pragma unroll
        for (int j = 0; j < 4; j++) { bvx[j] = bias[ocol + j * 8]; bvy[j] = bias[ocol + j * 8 + 1]; }
    }
    #pragma unroll
    for (int i = 0; i < 4; i++) {
        const int rA = orow + i * 16;
        const int rB = rA + 8;
        int sA = 0, sB = 0;
        if (ROPE) { sA = rA % S_; sB = rB % S_; }
        #pragma unroll
        for (int j = 0; j < 4; j++) {
            const int cc = ocol + j * 8;
            float v0 = acc[i][j][0], v1 = acc[i][j][1];
            float v2 = acc[i][j][2], v3 = acc[i][j][3];
            if (ROPE && cc < 1024) {
                int m = (cc & 63) >> 1;
                float freq = exp2f(-(float)(m >> 1) * L2T_OVER16);
                float pA = (m & 1) ? (float)(sA / 7) : (float)(sA % 7);
                float pB = (m & 1) ? (float)(sB / 7) : (float)(sB % 7);
                float snA, csA, snB, csB;
                sincosf(pA * freq, &snA, &csA);
                sincosf(pB * freq, &snB, &csB);
                float t0 = v0 * csA - v1 * snA, t1 = v0 * snA + v1 * csA;
                float t2 = v2 * csB - v3 * snB, t3 = v2 * snB + v3 * csB;
                v0 = t0; v1 = t1; v2 = t2; v3 = t3;
            }
            if (BIAS) { v0 += bvx[j]; v1 += bvy[j]; v2 += bvx[j]; v3 += bvy[j]; }
            *(float2*)(Cc + (size_t)rA * NCOLS + cc) = make_float2(v0, v1);
            *(float2*)(Cc + (size_t)rB * NCOLS + cc) = make_float2(v2, v3);
        }
    }
}

// ---------------- tensor-core windowed attention ----------------
#define T_QHI 0u
#define T_QLO 8192u
#define T_KK  16384u
#define T_VHI 24576u
#define T_VLO 32768u

__global__ __launch_bounds__(128) void attn_tc_kernel() {
    __shared__ __align__(1024) char sm[40960];
    const uint32_t sb = smem_u32(sm);

    const int tid  = threadIdx.x;
    const int lane = tid & 31;
    const int w    = tid >> 5;
    const int h    = blockIdx.x & 7;
    const int bg   = blockIdx.x >> 3;
    const size_t base = (size_t)bg * S_ * QKVN + h * 64;

    #pragma unroll
    for (int i = tid; i < 40960 / 16; i += 128)
        ((uint4*)sm)[i] = make_uint4(0, 0, 0, 0);
    __syncthreads();

    for (int i = tid; i < S_ * 16; i += 128) {
        int s   = i >> 4;
        int seg = i & 15;
        size_t ro = base + (size_t)s * QKVN + seg * 4;
        float4 q = *(const float4*)(g_qkv + ro);
        float4 k = *(const float4*)(g_qkv + ro + 512);
        float4 v = *(const float4*)(g_qkv + ro + 1024);
        int chunk = seg >> 1;
        uint32_t addr = (uint32_t)(s * 128 + ((chunk ^ (s & 7)) << 4) + (seg & 1) * 8);

        __half2 qh0, qh1, ql0, ql1;
        qh0.x = __float2half_rn(q.x); qh0.y = __float2half_rn(q.y);
        qh1.x = __float2half_rn(q.z); qh1.y = __float2half_rn(q.w);
        ql0.x = __float2half_rn(q.x - __half2float(qh0.x));
        ql0.y = __float2half_rn(q.y - __half2float(qh0.y));
        ql1.x = __float2half_rn(q.z - __half2float(qh1.x));
        ql1.y = __float2half_rn(q.w - __half2float(qh1.y));
        *(uint2*)(sm + T_QHI + addr) = make_uint2(*(uint32_t*)&qh0, *(uint32_t*)&qh1);
        *(uint2*)(sm + T_QLO + addr) = make_uint2(*(uint32_t*)&ql0, *(uint32_t*)&ql1);

        __half2 kh0, kh1;
        kh0.x = __float2half_rn(k.x); kh0.y = __float2half_rn(k.y);
        kh1.x = __float2half_rn(k.z); kh1.y = __float2half_rn(k.w);
        *(uint2*)(sm + T_KK + addr) = make_uint2(*(uint32_t*)&kh0, *(uint32_t*)&kh1);

        __half2 vh0, vh1, vl0, vl1;
        vh0.x = __float2half_rn(v.x); vh0.y = __float2half_rn(v.y);
        vh1.x = __float2half_rn(v.z); vh1.y = __float2half_rn(v.w);
        vl0.x = __float2half_rn(v.x - __half2float(vh0.x));
        vl0.y = __float2half_rn(v.y - __half2float(vh0.y));
        vl1.x = __float2half_rn(v.z - __half2float(vh1.x));
        vl1.y = __float2half_rn(v.w - __half2float(vh1.y));
        *(uint2*)(sm + T_VHI + addr) = make_uint2(*(uint32_t*)&vh0, *(uint32_t*)&vh1);
        *(uint2*)(sm + T_VLO + addr) = make_uint2(*(uint32_t*)&vl0, *(uint32_t*)&vl1);
    }
    __syncthreads();

    const int a_r  = w * 16 + (lane & 15);
    const int a_cp = lane >> 4;
    const int b_r0 = (lane & 7) + ((lane & 16) >> 1);
    const int b_cp = (lane >> 3) & 1;

    float sc[8][4];
    #pragma unroll
    for (int j = 0; j < 8; j++)
        #pragma unroll
        for (int p = 0; p < 4; p++) sc[j][p] = 0.0f;

    #pragma unroll
    for (int ks = 0; ks < 4; ks++) {
        uint32_t ahq[4], alq[4], bk[4][4];
        {
            int ch = 2 * ks + a_cp;
            uint32_t ad = sb + (uint32_t)(a_r * 128 + ((ch ^ (a_r & 7)) << 4));
            ldm4(ahq, ad + T_QHI);
            ldm4(alq, ad + T_QLO);
        }
        #pragma unroll
        for (int jn = 0; jn < 4; jn++) {
            int r  = jn * 16 + b_r0;
            int ch = 2 * ks + b_cp;
            ldm4(bk[jn], sb + T_KK + (uint32_t)(r * 128 + ((ch ^ (r & 7)) << 4)));
        }
        #pragma unroll
        for (int j = 0; j < 8; j++) {
            const uint32_t* bp = &bk[j >> 1][(j & 1) * 2];
            mma16816(sc[j], ahq, bp);
            mma16816(sc[j], alq, bp);
        }
    }

    #pragma unroll
    for (int j = 0; j < 8; j++) {
        int t0 = j * 8 + 2 * (lane & 3);
        sc[j][0] = (t0     < S_) ? sc[j][0] * SCALE_ : -1e30f;
        sc[j][1] = (t0 + 1 < S_) ? sc[j][1] * SCALE_ : -1e30f;
        sc[j][2] = (t0     < S_) ? sc[j][2] * SCALE_ : -1e30f;
        sc[j][3] = (t0 + 1 < S_) ? sc[j][3] * SCALE_ : -1e30f;
    }
    float mx0 = -1e30f, mx1 = -1e30f;
    #pragma unroll
    for (int j = 0; j < 8; j++) {
        mx0 = fmaxf(mx0, fmaxf(sc[j][0], sc[j][1]));
        mx1 = fmaxf(mx1, fmaxf(sc[j][2], sc[j][3]));
    }
    mx0 = fmaxf(mx0, __shfl_xor_sync(0xffffffffu, mx0, 1));
    mx0 = fmaxf(mx0, __shfl_xor_sync(0xffffffffu, mx0, 2));
    mx1 = fmaxf(mx1, __shfl_xor_sync(0xffffffffu, mx1, 1));
    mx1 = fmaxf(mx1, __shfl_xor_sync(0xffffffffu, mx1, 2));
    float sum0 = 0.0f, sum1 = 0.0f;
    #pragma unroll
    for (int j = 0; j < 8; j++) {
        sc[j][0] = __expf(sc[j][0] - mx0);
        sc[j][1] = __expf(sc[j][1] - mx0);
        sc[j][2] = __expf(sc[j][2] - mx1);
        sc[j][3] = __expf(sc[j][3] - mx1);
        sum0 += sc[j][0] + sc[j][1];
        sum1 += sc[j][2] + sc[j][3];
    }
    sum0 += __shfl_xor_sync(0xffffffffu, sum0, 1);
    sum0 += __shfl_xor_sync(0xffffffffu, sum0, 2);
    sum1 += __shfl_xor_sync(0xffffffffu, sum1, 1);
    sum1 += __shfl_xor_sync(0xffffffffu, sum1, 2);

    uint32_t pa[4][4];
    #pragma unroll
    for (int kt = 0; kt < 4; kt++) {
        __half2 t;
        t = __float22half2_rn(make_float2(sc[2*kt][0],   sc[2*kt][1]));   pa[kt][0] = *(uint32_t*)&t;
        t = __float22half2_rn(make_float2(sc[2*kt][2],   sc[2*kt][3]));   pa[kt][1] = *(uint32_t*)&t;
        t = __float22half2_rn(make_float2(sc[2*kt+1][0], sc[2*kt+1][1])); pa[kt][2] = *(uint32_t*)&t;
        t = __float22half2_rn(make_float2(sc[2*kt+1][2], sc[2*kt+1][3])); pa[kt][3] = *(uint32_t*)&t;
    }

    float oacc[8][4];
    #pragma unroll
    for (int nb = 0; nb < 8; nb++)
        #pragma unroll
        for (int p = 0; p < 4; p++) oacc[nb][p] = 0.0f;

    #pragma unroll
    for (int kt = 0; kt < 4; kt++) {
        uint32_t bvh[4][4], bvl[4][4];
        #pragma unroll
        for (int ii = 0; ii < 4; ii++) {
            int rowk  = kt * 16 + ((lane >> 3) & 1) * 8 + (lane & 7);
            int chunk = 2 * ii + (lane >> 4);
            uint32_t ad = sb + (uint32_t)(rowk * 128 + ((chunk ^ (rowk & 7)) << 4));
            ldm4t(bvh[ii], ad + T_VHI);
            ldm4t(bvl[ii], ad + T_VLO);
        }
        #pragma unroll
        for (int nb = 0; nb < 8; nb++) {
            mma16816(oacc[nb], pa[kt], &bvh[nb >> 1][(nb & 1) * 2]);
            mma16816(oacc[nb], pa[kt], &bvl[nb >> 1][(nb & 1) * 2]);
        }
    }

    const float inv0 = 1.0f / sum0;
    const float inv1 = 1.0f / sum1;
    const int g = bg & 63;
    const int b = bg >> 6;
    const int s0 = w * 16 + (lane >> 2);
    const int s1 = s0 + 8;
    const int colb = 2 * (lane & 3);

    #pragma unroll
    for (int half = 0; half < 2; half++) {
        int s = half ? s1 : s0;
        if (s >= S_) continue;
        float inv = half ? inv1 : inv0;
        int sy = s / 7, sx = s - sy * 7;
        int n  = ((g >> 3) * 7 + sy) * 56 + (g & 7) * 7 + sx;
        size_t off = ((size_t)(b * NTOK + n)) * C_ + h * 64;
        #pragma unroll
        for (int nb = 0; nb < 8; nb++) {
            float o0 = oacc[nb][half * 2]     * inv;
            float o1 = oacc[nb][half * 2 + 1] * inv;
            __half2 hv, lv;
            hv.x = __float2half_rn(o0);
            hv.y = __float2half_rn(o1);
            lv.x = __float2half_rn(o0 - __half2float(hv.x));
            lv.y = __float2half_rn(o1 - __half2float(hv.y));
            size_t co = off + nb * 8 + colb;
            *(uint32_t*)(g_ahi + co) = *(uint32_t*)&hv;
            *(uint32_t*)(g_alo + co) = *(uint32_t*)&lv;
        }
    }
}

// ---------------- launch ----------------
extern "C" void kernel_launch(void* const* d_in, const int* in_sizes, int n_in,
                              void* d_out, int out_size)
{
    const float* x      = (const float*)d_in[0];
    const float* w_qkv  = (const float*)d_in[1];
    const float* w_proj = (const float*)d_in[2];
    const float* b_proj = (const float*)d_in[3];
    float* out = (float*)d_out;

    void *qkvp, *xhp, *whp, *php, *ahip, *alop;
    cudaGetSymbolAddress(&qkvp, g_qkv);
    cudaGetSymbolAddress(&xhp, g_xh);
    cudaGetSymbolAddress(&whp, g_wh);   cudaGetSymbolAddress(&php, g_ph);
    cudaGetSymbolAddress(&ahip, g_ahi); cudaGetSymbolAddress(&alop, g_alo);

    cudaFuncSetAttribute(mma_gemm<QKVN, false, true, 1>,
                         cudaFuncAttributeMaxDynamicSharedMemorySize, DYN_SMEM);
    cudaFuncSetAttribute(mma_gemm<C_, true, false, 2>,
                         cudaFuncAttributeMaxDynamicSharedMemorySize, DYN_SMEM);

    // 0) conversions
    conv_x_kernel<<<M_ * 128 / 256, 256>>>(x);
    conv_w_kernel<<<QKVN * C_ / 4 / 256, 256>>>(w_qkv, (__half*)whp);
    conv_w_kernel<<<C_ * C_ / 4 / 256, 256>>>(w_proj, (__half*)php);

    // 1) QKV GEMM (single-term fp16 HMMA) with fused RoPE in epilogue
    dim3 g1(QKVN / 128, M_ / 128);
    mma_gemm<QKVN, false, true, 1><<<g1, 256, DYN_SMEM>>>(
        (const __half*)xhp, nullptr, (const __half*)whp,
        nullptr, (float*)qkvp);

    // 2) tensor-core windowed attention
    attn_tc_kernel<<<B_ * G_ * NH, 128>>>();

    // 3) projection GEMM + bias (2-term split-fp16)
    dim3 g2(C_ / 128, M_ / 128);
    mma_gemm<C_, true, false, 2><<<g2, 256, DYN_SMEM>>>(
        (const __half*)ahip, (const __half*)alop, (const __half*)php,
        b_proj, out);
}

// round 10
// speedup vs baseline: 4.3810x; 1.1714x over previous
#include <cuda_runtime.h>
#include <cuda_fp16.h>
#include <cstdint>
#include <cstddef>

// ---------------- problem constants ----------------
#define B_    32
#define NTOK  3136
#define C_    512
#define NH    8
#define S_    49
#define G_    64
#define M_    (B_*G_*S_)    // 100352 (784*128)
#define QKVN  1536
#define SCALE_ 0.125f
#define L2T_OVER16 0.8304820237218406f

// ---------------- scratch ----------------
__device__ float g_qkv[(size_t)M_ * QKVN];       // fp32 qkv (roped), (b,g,s) rows
__device__ __half g_xh[(size_t)M_ * C_];         // gathered x, fp16
__device__ __half g_wh[QKVN * C_];               // w_qkv, fp16
__device__ __half g_ph[C_ * C_];                 // w_proj, fp16
__device__ __half g_ah[(size_t)M_ * C_];         // attention out, fp16, (b,n) rows

// row r (in b,g,s order) -> x row offset (b,n)
__device__ __forceinline__ size_t gather_row_off(int r) {
    int b   = r / (G_ * S_);
    int rem = r - b * (G_ * S_);
    int g   = rem / S_;
    int s   = rem - g * S_;
    int sy  = s / 7;
    int sx  = s - sy * 7;
    int n   = ((g >> 3) * 7 + sy) * 56 + (g & 7) * 7 + sx;
    return ((size_t)b * NTOK + n) * C_;
}

// ---------------- asm wrappers ----------------
__device__ __forceinline__ uint32_t smem_u32(const void* p) {
    uint32_t a;
    asm("{ .reg .u64 t; cvta.to.shared.u64 t, %1; cvt.u32.u64 %0, t; }" : "=r"(a) : "l"(p));
    return a;
}
__device__ __forceinline__ void cp16(uint32_t saddr, const void* g) {
    asm volatile("cp.async.cg.shared.global [%0], [%1], 16;" :: "r"(saddr), "l"(g));
}
__device__ __forceinline__ void cp_commit() {
    asm volatile("cp.async.commit_group;" ::: "memory");
}
__device__ __forceinline__ void cp_wait0() {
    asm volatile("cp.async.wait_group 0;" ::: "memory");
}
__device__ __forceinline__ void cp_wait1() {
    asm volatile("cp.async.wait_group 1;" ::: "memory");
}
__device__ __forceinline__ void ldm4(uint32_t* r, uint32_t addr) {
    asm volatile("ldmatrix.sync.aligned.m8n8.x4.shared.b16 {%0,%1,%2,%3}, [%4];"
        : "=r"(r[0]), "=r"(r[1]), "=r"(r[2]), "=r"(r[3]) : "r"(addr));
}
__device__ __forceinline__ void ldm4t(uint32_t* r, uint32_t addr) {
    asm volatile("ldmatrix.sync.aligned.m8n8.x4.trans.shared.b16 {%0,%1,%2,%3}, [%4];"
        : "=r"(r[0]), "=r"(r[1]), "=r"(r[2]), "=r"(r[3]) : "r"(addr));
}
__device__ __forceinline__ void mma16816(float* c, const uint32_t* a, const uint32_t* b) {
    asm volatile("mma.sync.aligned.m16n8k16.row.col.f32.f16.f16.f32 "
        "{%0,%1,%2,%3}, {%4,%5,%6,%7}, {%8,%9}, {%0,%1,%2,%3};"
        : "+f"(c[0]), "+f"(c[1]), "+f"(c[2]), "+f"(c[3])
        : "r"(a[0]), "r"(a[1]), "r"(a[2]), "r"(a[3]), "r"(b[0]), "r"(b[1]));
}

// ---------------- conversion kernels ----------------
__global__ __launch_bounds__(256) void conv_x_kernel(const float* __restrict__ x) {
    int idx = blockIdx.x * 256 + threadIdx.x;       // M_*128 threads
    int r = idx >> 7;
    int q = (idx & 127) << 2;
    float4 v = *(const float4*)(x + gather_row_off(r) + q);
    __half2 a, b;
    a.x = __float2half_rn(v.x); a.y = __float2half_rn(v.y);
    b.x = __float2half_rn(v.z); b.y = __float2half_rn(v.w);
    size_t o = (size_t)r * C_ + q;
    *(uint2*)(g_xh + o) = make_uint2(*(uint32_t*)&a, *(uint32_t*)&b);
}

__global__ __launch_bounds__(256) void conv_w_kernel(const float* __restrict__ w,
                                                     __half* __restrict__ h) {
    int idx = blockIdx.x * 256 + threadIdx.x;
    size_t o = (size_t)idx << 2;
    float4 v = *(const float4*)(w + o);
    __half2 a, b;
    a.x = __float2half_rn(v.x); a.y = __float2half_rn(v.y);
    b.x = __float2half_rn(v.z); b.y = __float2half_rn(v.w);
    *(uint2*)(h + o) = make_uint2(*(uint32_t*)&a, *(uint32_t*)&b);
}

// ---------------- fp16 HMMA GEMM (single term) ----------------
// C[r][d] = sum_k A[r][k]*B[d][k] (+bias / +rope), K=512
// block 128x128, 8 warps (2x4), warp tile 64x32, BK=32, 3-stage cp.async
// smem per stage: A(8K) pad(8K) B(8K)
#define STG_BYTES 24576u
#define NSTG 3
#define DYN_SMEM (NSTG * STG_BYTES)

template <int NCOLS, bool BIAS, bool ROPE>
__global__ __launch_bounds__(256, 2) void mma_gemm(
    const __half* __restrict__ Am, const __half* __restrict__ Bm,
    const float* __restrict__ bias, float* __restrict__ Cc)
{
    extern __shared__ __align__(1024) char dyn[];
    const uint32_t sbase = smem_u32(dyn);

    const int tid  = threadIdx.x;
    const int lane = tid & 31;
    const int wid  = tid >> 5;
    const int wm   = wid >> 2;
    const int wn   = wid & 3;
    const int bm   = blockIdx.y * 128;
    const int bn   = blockIdx.x * 128;

    const int grp  = tid >> 6;          // 0:A 2:B, others idle
    const int prow = tid & 63;
    const __half* gsrc = nullptr;
    if      (grp == 0) gsrc = Am + (size_t)bm * C_;
    else if (grp == 2) gsrc = Bm + (size_t)bn * C_;
    const __half* grow = gsrc ? gsrc + (size_t)(2 * prow) * C_ : nullptr;
    const uint32_t smat = sbase + grp * 8192u + prow * 128u;
    const int sx = prow & 7;

    auto load_stage = [&](int st, int kc) {
        if (grow) {
            const char* g0 = (const char*)(grow + kc * 32);
            uint32_t rb = smat + (uint32_t)st * STG_BYTES;
            #pragma unroll
            for (int c = 0; c < 8; c++)
                cp16(rb + (uint32_t)((c ^ sx) << 4), g0 + (c >> 2) * (C_ * 2) + (c & 3) * 16);
        }
    };

    const int a_r  = wm * 64 + (lane & 15);
    const int a_cp = lane >> 4;
    const int b_r0 = wn * 32 + (lane & 7) + ((lane & 16) >> 1);
    const int b_cp = (lane >> 3) & 1;

    uint32_t aoff[2][4], boff[2][2];
    #pragma unroll
    for (int ks = 0; ks < 2; ks++) {
        #pragma unroll
        for (int i = 0; i < 4; i++) {
            int r  = a_r + i * 16;
            int pr = r >> 1;
            int pc = ((r & 1) << 2) + 2 * ks + a_cp;
            aoff[ks][i] = (uint32_t)(pr * 128 + ((pc ^ (pr & 7)) << 4));
        }
        #pragma unroll
        for (int jj = 0; jj < 2; jj++) {
            int r  = b_r0 + jj * 16;
            int pr = r >> 1;
            int pc = ((r & 1) << 2) + 2 * ks + b_cp;
            boff[ks][jj] = 16384u + (uint32_t)(pr * 128 + ((pc ^ (pr & 7)) << 4));
        }
    }

    float acc[4][4][4];
    #pragma unroll
    for (int i = 0; i < 4; i++)
        #pragma unroll
        for (int j = 0; j < 4; j++)
            #pragma unroll
            for (int p = 0; p < 4; p++) acc[i][j][p] = 0.0f;

    load_stage(0, 0); cp_commit();
    load_stage(1, 1); cp_commit();

    uint32_t ah[2][4][4], bf[2][2][4];

    auto load_frags = [&](int buf, uint32_t base, int ks) {
        #pragma unroll
        for (int i = 0; i < 4; i++)
            ldm4(ah[buf][i], base + aoff[ks][i]);
        #pragma unroll
        for (int jj = 0; jj < 2; jj++)
            ldm4(bf[buf][jj], base + boff[ks][jj]);
    };
    auto do_mmas = [&](int buf) {
        #pragma unroll
        for (int i = 0; i < 4; i++)
            #pragma unroll
            for (int j = 0; j < 4; j++)
                mma16816(acc[i][j], ah[buf][i], &bf[buf][j >> 1][(j & 1) * 2]);
    };

    #pragma unroll 1
    for (int kc = 0; kc < 16; kc++) {
        if (kc < 15) cp_wait1(); else cp_wait0();
        __syncthreads();
        if (kc + 2 < 16) { load_stage((kc + 2) % NSTG, kc + 2); cp_commit(); }

        const uint32_t base = sbase + (uint32_t)(kc % NSTG) * STG_BYTES;
        load_frags(0, base, 0);
        load_frags(1, base, 1);
        do_mmas(0);
        do_mmas(1);
    }

    const int orow = bm + wm * 64 + (lane >> 2);
    const int ocol = bn + wn * 32 + (lane & 3) * 2;
    float bvx[4], bvy[4];
    if (BIAS) {
        #pragma unroll
        for (int j = 0; j < 4; j++) { bvx[j] = bias[ocol + j * 8]; bvy[j] = bias[ocol + j * 8 + 1]; }
    }
    #pragma unroll
    for (int i = 0; i < 4; i++) {
        const int rA = orow + i * 16;
        const int rB = rA + 8;
        int sA = 0, sB = 0;
        if (ROPE) { sA = rA % S_; sB = rB % S_; }
        #pragma unroll
        for (int j = 0; j < 4; j++) {
            const int cc = ocol + j * 8;
            float v0 = acc[i][j][0], v1 = acc[i][j][1];
            float v2 = acc[i][j][2], v3 = acc[i][j][3];
            if (ROPE && cc < 1024) {
                int m = (cc & 63) >> 1;
                float freq = exp2f(-(float)(m >> 1) * L2T_OVER16);
                float pA = (m & 1) ? (float)(sA / 7) : (float)(sA % 7);
                float pB = (m & 1) ? (float)(sB / 7) : (float)(sB % 7);
                float snA, csA, snB, csB;
                sincosf(pA * freq, &snA, &csA);
                sincosf(pB * freq, &snB, &csB);
                float t0 = v0 * csA - v1 * snA, t1 = v0 * snA + v1 * csA;
                float t2 = v2 * csB - v3 * snB, t3 = v2 * snB + v3 * csB;
                v0 = t0; v1 = t1; v2 = t2; v3 = t3;
            }
            if (BIAS) { v0 += bvx[j]; v1 += bvy[j]; v2 += bvx[j]; v3 += bvy[j]; }
            *(float2*)(Cc + (size_t)rA * NCOLS + cc) = make_float2(v0, v1);
            *(float2*)(Cc + (size_t)rB * NCOLS + cc) = make_float2(v2, v3);
        }
    }
}

// ---------------- tensor-core windowed attention (single fp16) ----------------
// one block per (b,g,h), 128 threads / 4 warps; S=49 padded to 64.
// smem tiles (64 rows x 128B, xor swizzle): QH 0, KK 8192, VH 16384
#define T_QH 0u
#define T_KK 8192u
#define T_VH 16384u

__global__ __launch_bounds__(128) void attn_tc_kernel() {
    __shared__ __align__(1024) char sm[24576];
    const uint32_t sb = smem_u32(sm);

    const int tid  = threadIdx.x;
    const int lane = tid & 31;
    const int w    = tid >> 5;
    const int h    = blockIdx.x & 7;
    const int bg   = blockIdx.x >> 3;
    const size_t base = (size_t)bg * S_ * QKVN + h * 64;

    // zero-fill (padding rows must be 0)
    #pragma unroll
    for (int i = tid; i < 24576 / 16; i += 128)
        ((uint4*)sm)[i] = make_uint4(0, 0, 0, 0);
    __syncthreads();

    // fill rows 0..48: q,k,v -> fp16
    for (int i = tid; i < S_ * 16; i += 128) {
        int s   = i >> 4;
        int seg = i & 15;
        size_t ro = base + (size_t)s * QKVN + seg * 4;
        float4 q = *(const float4*)(g_qkv + ro);
        float4 k = *(const float4*)(g_qkv + ro + 512);
        float4 v = *(const float4*)(g_qkv + ro + 1024);
        int chunk = seg >> 1;
        uint32_t addr = (uint32_t)(s * 128 + ((chunk ^ (s & 7)) << 4) + (seg & 1) * 8);

        __half2 a0, a1;
        a0.x = __float2half_rn(q.x); a0.y = __float2half_rn(q.y);
        a1.x = __float2half_rn(q.z); a1.y = __float2half_rn(q.w);
        *(uint2*)(sm + T_QH + addr) = make_uint2(*(uint32_t*)&a0, *(uint32_t*)&a1);

        a0.x = __float2half_rn(k.x); a0.y = __float2half_rn(k.y);
        a1.x = __float2half_rn(k.z); a1.y = __float2half_rn(k.w);
        *(uint2*)(sm + T_KK + addr) = make_uint2(*(uint32_t*)&a0, *(uint32_t*)&a1);

        a0.x = __float2half_rn(v.x); a0.y = __float2half_rn(v.y);
        a1.x = __float2half_rn(v.z); a1.y = __float2half_rn(v.w);
        *(uint2*)(sm + T_VH + addr) = make_uint2(*(uint32_t*)&a0, *(uint32_t*)&a1);
    }
    __syncthreads();

    // ---- QK^T: warp w -> score rows w*16..w*16+15, cols 0..63 ----
    const int a_r  = w * 16 + (lane & 15);
    const int a_cp = lane >> 4;
    const int b_r0 = (lane & 7) + ((lane & 16) >> 1);
    const int b_cp = (lane >> 3) & 1;

    float sc[8][4];
    #pragma unroll
    for (int j = 0; j < 8; j++)
        #pragma unroll
        for (int p = 0; p < 4; p++) sc[j][p] = 0.0f;

    #pragma unroll
    for (int ks = 0; ks < 4; ks++) {
        uint32_t aq[4], bk[4][4];
        {
            int ch = 2 * ks + a_cp;
            ldm4(aq, sb + T_QH + (uint32_t)(a_r * 128 + ((ch ^ (a_r & 7)) << 4)));
        }
        #pragma unroll
        for (int jn = 0; jn < 4; jn++) {
            int r  = jn * 16 + b_r0;
            int ch = 2 * ks + b_cp;
            ldm4(bk[jn], sb + T_KK + (uint32_t)(r * 128 + ((ch ^ (r & 7)) << 4)));
        }
        #pragma unroll
        for (int j = 0; j < 8; j++)
            mma16816(sc[j], aq, &bk[j >> 1][(j & 1) * 2]);
    }

    // ---- register softmax (rows r0 = w*16 + lane>>2, r1 = r0+8) ----
    #pragma unroll
    for (int j = 0; j < 8; j++) {
        int t0 = j * 8 + 2 * (lane & 3);
        sc[j][0] = (t0     < S_) ? sc[j][0] * SCALE_ : -1e30f;
        sc[j][1] = (t0 + 1 < S_) ? sc[j][1] * SCALE_ : -1e30f;
        sc[j][2] = (t0     < S_) ? sc[j][2] * SCALE_ : -1e30f;
        sc[j][3] = (t0 + 1 < S_) ? sc[j][3] * SCALE_ : -1e30f;
    }
    float mx0 = -1e30f, mx1 = -1e30f;
    #pragma unroll
    for (int j = 0; j < 8; j++) {
        mx0 = fmaxf(mx0, fmaxf(sc[j][0], sc[j][1]));
        mx1 = fmaxf(mx1, fmaxf(sc[j][2], sc[j][3]));
    }
    mx0 = fmaxf(mx0, __shfl_xor_sync(0xffffffffu, mx0, 1));
    mx0 = fmaxf(mx0, __shfl_xor_sync(0xffffffffu, mx0, 2));
    mx1 = fmaxf(mx1, __shfl_xor_sync(0xffffffffu, mx1, 1));
    mx1 = fmaxf(mx1, __shfl_xor_sync(0xffffffffu, mx1, 2));
    float sum0 = 0.0f, sum1 = 0.0f;
    #pragma unroll
    for (int j = 0; j < 8; j++) {
        sc[j][0] = __expf(sc[j][0] - mx0);
        sc[j][1] = __expf(sc[j][1] - mx0);
        sc[j][2] = __expf(sc[j][2] - mx1);
        sc[j][3] = __expf(sc[j][3] - mx1);
        sum0 += sc[j][0] + sc[j][1];
        sum1 += sc[j][2] + sc[j][3];
    }
    sum0 += __shfl_xor_sync(0xffffffffu, sum0, 1);
    sum0 += __shfl_xor_sync(0xffffffffu, sum0, 2);
    sum1 += __shfl_xor_sync(0xffffffffu, sum1, 1);
    sum1 += __shfl_xor_sync(0xffffffffu, sum1, 2);

    // ---- pack P (unnormalized) as fp16 A fragments ----
    uint32_t pa[4][4];
    #pragma unroll
    for (int kt = 0; kt < 4; kt++) {
        __half2 t;
        t = __float22half2_rn(make_float2(sc[2*kt][0],   sc[2*kt][1]));   pa[kt][0] = *(uint32_t*)&t;
        t = __float22half2_rn(make_float2(sc[2*kt][2],   sc[2*kt][3]));   pa[kt][1] = *(uint32_t*)&t;
        t = __float22half2_rn(make_float2(sc[2*kt+1][0], sc[2*kt+1][1])); pa[kt][2] = *(uint32_t*)&t;
        t = __float22half2_rn(make_float2(sc[2*kt+1][2], sc[2*kt+1][3])); pa[kt][3] = *(uint32_t*)&t;
    }

    // ---- PV ----
    float oacc[8][4];
    #pragma unroll
    for (int nb = 0; nb < 8; nb++)
        #pragma unroll
        for (int p = 0; p < 4; p++) oacc[nb][p] = 0.0f;

    #pragma unroll
    for (int kt = 0; kt < 4; kt++) {
        uint32_t bv[4][4];
        #pragma unroll
        for (int ii = 0; ii < 4; ii++) {
            int rowk  = kt * 16 + ((lane >> 3) & 1) * 8 + (lane & 7);
            int chunk = 2 * ii + (lane >> 4);
            ldm4t(bv[ii], sb + T_VH + (uint32_t)(rowk * 128 + ((chunk ^ (rowk & 7)) << 4)));
        }
        #pragma unroll
        for (int nb = 0; nb < 8; nb++)
            mma16816(oacc[nb], pa[kt], &bv[nb >> 1][(nb & 1) * 2]);
    }

    // ---- normalize + scatter to (b,n,c), fp16 ----
    const float inv0 = 1.0f / sum0;
    const float inv1 = 1.0f / sum1;
    const int g = bg & 63;
    const int b = bg >> 6;
    const int s0 = w * 16 + (lane >> 2);
    const int s1 = s0 + 8;
    const int colb = 2 * (lane & 3);

    #pragma unroll
    for (int half = 0; half < 2; half++) {
        int s = half ? s1 : s0;
        if (s >= S_) continue;
        float inv = half ? inv1 : inv0;
        int sy = s / 7, sx = s - sy * 7;
        int n  = ((g >> 3) * 7 + sy) * 56 + (g & 7) * 7 + sx;
        size_t off = ((size_t)(b * NTOK + n)) * C_ + h * 64;
        #pragma unroll
        for (int nb = 0; nb < 8; nb++) {
            __half2 hv;
            hv.x = __float2half_rn(oacc[nb][half * 2]     * inv);
            hv.y = __float2half_rn(oacc[nb][half * 2 + 1] * inv);
            *(uint32_t*)(g_ah + off + nb * 8 + colb) = *(uint32_t*)&hv;
        }
    }
}

// ---------------- launch ----------------
extern "C" void kernel_launch(void* const* d_in, const int* in_sizes, int n_in,
                              void* d_out, int out_size)
{
    const float* x      = (const float*)d_in[0];
    const float* w_qkv  = (const float*)d_in[1];
    const float* w_proj = (const float*)d_in[2];
    const float* b_proj = (const float*)d_in[3];
    float* out = (float*)d_out;

    void *qkvp, *xhp, *whp, *php, *ahp;
    cudaGetSymbolAddress(&qkvp, g_qkv);
    cudaGetSymbolAddress(&xhp, g_xh);
    cudaGetSymbolAddress(&whp, g_wh);
    cudaGetSymbolAddress(&php, g_ph);
    cudaGetSymbolAddress(&ahp, g_ah);

    cudaFuncSetAttribute(mma_gemm<QKVN, false, true>,
                         cudaFuncAttributeMaxDynamicSharedMemorySize, DYN_SMEM);
    cudaFuncSetAttribute(mma_gemm<C_, true, false>,
                         cudaFuncAttributeMaxDynamicSharedMemorySize, DYN_SMEM);

    // 0) conversions
    conv_x_kernel<<<M_ * 128 / 256, 256>>>(x);
    conv_w_kernel<<<QKVN * C_ / 4 / 256, 256>>>(w_qkv, (__half*)whp);
    conv_w_kernel<<<C_ * C_ / 4 / 256, 256>>>(w_proj, (__half*)php);

    // 1) QKV GEMM (fp16 HMMA) with fused RoPE in epilogue
    dim3 g1(QKVN / 128, M_ / 128);
    mma_gemm<QKVN, false, true><<<g1, 256, DYN_SMEM>>>(
        (const __half*)xhp, (const __half*)whp, nullptr, (float*)qkvp);

    // 2) tensor-core windowed attention
    attn_tc_kernel<<<B_ * G_ * NH, 128>>>();

    // 3) projection GEMM + bias (fp16 HMMA)
    dim3 g2(C_ / 128, M_ / 128);
    mma_gemm<C_, true, false><<<g2, 256, DYN_SMEM>>>(
        (const __half*)ahp, (const __half*)php, b_proj, out);
}

// round 11
// speedup vs baseline: 4.5362x; 1.0354x over previous
#include <cuda_runtime.h>
#include <cuda_fp16.h>
#include <cstdint>
#include <cstddef>

// ---------------- problem constants ----------------
#define B_    32
#define NTOK  3136
#define C_    512
#define NH    8
#define S_    49
#define G_    64
#define M_    (B_*G_*S_)    // 100352 (784*128)
#define QKVN  1536
#define SCALE_ 0.125f
#define L2T_OVER16 0.8304820237218406f

// ---------------- scratch ----------------
__device__ __half g_qkv[(size_t)M_ * QKVN];      // fp16 qkv (roped), (b,g,s) rows
__device__ __half g_xh[(size_t)M_ * C_];         // gathered x, fp16
__device__ __half g_wh[QKVN * C_];               // w_qkv, fp16
__device__ __half g_ph[C_ * C_];                 // w_proj, fp16
__device__ __half g_ah[(size_t)M_ * C_];         // attention out, fp16, (b,n) rows

// row r (in b,g,s order) -> x row offset (b,n)
__device__ __forceinline__ size_t gather_row_off(int r) {
    int b   = r / (G_ * S_);
    int rem = r - b * (G_ * S_);
    int g   = rem / S_;
    int s   = rem - g * S_;
    int sy  = s / 7;
    int sx  = s - sy * 7;
    int n   = ((g >> 3) * 7 + sy) * 56 + (g & 7) * 7 + sx;
    return ((size_t)b * NTOK + n) * C_;
}

// ---------------- asm wrappers ----------------
__device__ __forceinline__ uint32_t smem_u32(const void* p) {
    uint32_t a;
    asm("{ .reg .u64 t; cvta.to.shared.u64 t, %1; cvt.u32.u64 %0, t; }" : "=r"(a) : "l"(p));
    return a;
}
__device__ __forceinline__ void cp16(uint32_t saddr, const void* g) {
    asm volatile("cp.async.cg.shared.global [%0], [%1], 16;" :: "r"(saddr), "l"(g));
}
__device__ __forceinline__ void cp_commit() {
    asm volatile("cp.async.commit_group;" ::: "memory");
}
__device__ __forceinline__ void cp_wait0() {
    asm volatile("cp.async.wait_group 0;" ::: "memory");
}
__device__ __forceinline__ void cp_wait1() {
    asm volatile("cp.async.wait_group 1;" ::: "memory");
}
__device__ __forceinline__ void cp_wait2() {
    asm volatile("cp.async.wait_group 2;" ::: "memory");
}
__device__ __forceinline__ void ldm4(uint32_t* r, uint32_t addr) {
    asm volatile("ldmatrix.sync.aligned.m8n8.x4.shared.b16 {%0,%1,%2,%3}, [%4];"
        : "=r"(r[0]), "=r"(r[1]), "=r"(r[2]), "=r"(r[3]) : "r"(addr));
}
__device__ __forceinline__ void ldm4t(uint32_t* r, uint32_t addr) {
    asm volatile("ldmatrix.sync.aligned.m8n8.x4.trans.shared.b16 {%0,%1,%2,%3}, [%4];"
        : "=r"(r[0]), "=r"(r[1]), "=r"(r[2]), "=r"(r[3]) : "r"(addr));
}
__device__ __forceinline__ void mma16816(float* c, const uint32_t* a, const uint32_t* b) {
    asm volatile("mma.sync.aligned.m16n8k16.row.col.f32.f16.f16.f32 "
        "{%0,%1,%2,%3}, {%4,%5,%6,%7}, {%8,%9}, {%0,%1,%2,%3};"
        : "+f"(c[0]), "+f"(c[1]), "+f"(c[2]), "+f"(c[3])
        : "r"(a[0]), "r"(a[1]), "r"(a[2]), "r"(a[3]), "r"(b[0]), "r"(b[1]));
}

// ---------------- conversion kernels ----------------
__global__ __launch_bounds__(256) void conv_x_kernel(const float* __restrict__ x) {
    int idx = blockIdx.x * 256 + threadIdx.x;       // M_*128 threads
    int r = idx >> 7;
    int q = (idx & 127) << 2;
    float4 v = *(const float4*)(x + gather_row_off(r) + q);
    __half2 a, b;
    a.x = __float2half_rn(v.x); a.y = __float2half_rn(v.y);
    b.x = __float2half_rn(v.z); b.y = __float2half_rn(v.w);
    size_t o = (size_t)r * C_ + q;
    *(uint2*)(g_xh + o) = make_uint2(*(uint32_t*)&a, *(uint32_t*)&b);
}

__global__ __launch_bounds__(256) void conv_w_kernel(const float* __restrict__ w,
                                                     __half* __restrict__ h) {
    int idx = blockIdx.x * 256 + threadIdx.x;
    size_t o = (size_t)idx << 2;
    float4 v = *(const float4*)(w + o);
    __half2 a, b;
    a.x = __float2half_rn(v.x); a.y = __float2half_rn(v.y);
    b.x = __float2half_rn(v.z); b.y = __float2half_rn(v.w);
    *(uint2*)(h + o) = make_uint2(*(uint32_t*)&a, *(uint32_t*)&b);
}

// ---------------- fp16 HMMA GEMM ----------------
// C[r][d] = sum_k A[r][k]*B[d][k] (+bias / +rope), K=512
// block 128x128, 8 warps (2x4), warp tile 64x32, BK=32, 4-stage cp.async
// Tiles row-paired: 2 logical rows (64B) per 128B physical row, xor swizzle.
// smem per stage: A(8K) pad(8K) B(8K)
#define STG_BYTES 24576u
#define NSTG 4
#define DYN_SMEM (NSTG * STG_BYTES)

// HALFOUT: write __half output (with fused RoPE); else fp32 (+bias)
template <int NCOLS, bool BIAS, bool ROPE, bool HALFOUT>
__global__ __launch_bounds__(256, 2) void mma_gemm(
    const __half* __restrict__ Am, const __half* __restrict__ Bm,
    const float* __restrict__ bias, void* __restrict__ Cout)
{
    extern __shared__ __align__(1024) char dyn[];
    const uint32_t sbase = smem_u32(dyn);

    const int tid  = threadIdx.x;
    const int lane = tid & 31;
    const int wid  = tid >> 5;
    const int wm   = wid >> 2;
    const int wn   = wid & 3;
    const int bm   = blockIdx.y * 128;
    const int bn   = blockIdx.x * 128;

    const int grp  = tid >> 6;          // 0:A 2:B, others idle
    const int prow = tid & 63;
    const __half* gsrc = nullptr;
    if      (grp == 0) gsrc = Am + (size_t)bm * C_;
    else if (grp == 2) gsrc = Bm + (size_t)bn * C_;
    const __half* grow = gsrc ? gsrc + (size_t)(2 * prow) * C_ : nullptr;
    const uint32_t smat = sbase + grp * 8192u + prow * 128u;
    const int sx = prow & 7;

    auto load_stage = [&](int st, int kc) {
        if (grow) {
            const char* g0 = (const char*)(grow + kc * 32);
            uint32_t rb = smat + (uint32_t)st * STG_BYTES;
            #pragma unroll
            for (int c = 0; c < 8; c++)
                cp16(rb + (uint32_t)((c ^ sx) << 4), g0 + (c >> 2) * (C_ * 2) + (c & 3) * 16);
        }
    };

    const int a_r  = wm * 64 + (lane & 15);
    const int a_cp = lane >> 4;
    const int b_r0 = wn * 32 + (lane & 7) + ((lane & 16) >> 1);
    const int b_cp = (lane >> 3) & 1;

    uint32_t aoff[2][4], boff[2][2];
    #pragma unroll
    for (int ks = 0; ks < 2; ks++) {
        #pragma unroll
        for (int i = 0; i < 4; i++) {
            int r  = a_r + i * 16;
            int pr = r >> 1;
            int pc = ((r & 1) << 2) + 2 * ks + a_cp;
            aoff[ks][i] = (uint32_t)(pr * 128 + ((pc ^ (pr & 7)) << 4));
        }
        #pragma unroll
        for (int jj = 0; jj < 2; jj++) {
            int r  = b_r0 + jj * 16;
            int pr = r >> 1;
            int pc = ((r & 1) << 2) + 2 * ks + b_cp;
            boff[ks][jj] = 16384u + (uint32_t)(pr * 128 + ((pc ^ (pr & 7)) << 4));
        }
    }

    float acc[4][4][4];
    #pragma unroll
    for (int i = 0; i < 4; i++)
        #pragma unroll
        for (int j = 0; j < 4; j++)
            #pragma unroll
            for (int p = 0; p < 4; p++) acc[i][j][p] = 0.0f;

    load_stage(0, 0); cp_commit();
    load_stage(1, 1); cp_commit();
    load_stage(2, 2); cp_commit();

    uint32_t ah[2][4][4], bf[2][2][4];

    auto load_frags = [&](int buf, uint32_t base, int ks) {
        #pragma unroll
        for (int i = 0; i < 4; i++)
            ldm4(ah[buf][i], base + aoff[ks][i]);
        #pragma unroll
        for (int jj = 0; jj < 2; jj++)
            ldm4(bf[buf][jj], base + boff[ks][jj]);
    };
    auto do_mmas = [&](int buf) {
        #pragma unroll
        for (int i = 0; i < 4; i++)
            #pragma unroll
            for (int j = 0; j < 4; j++)
                mma16816(acc[i][j], ah[buf][i], &bf[buf][j >> 1][(j & 1) * 2]);
    };

    #pragma unroll 1
    for (int kc = 0; kc < 16; kc++) {
        if      (kc <= 13) cp_wait2();
        else if (kc == 14) cp_wait1();
        else               cp_wait0();
        __syncthreads();
        if (kc + 3 < 16) { load_stage((kc + 3) % NSTG, kc + 3); cp_commit(); }

        const uint32_t base = sbase + (uint32_t)(kc % NSTG) * STG_BYTES;
        load_frags(0, base, 0);
        load_frags(1, base, 1);
        do_mmas(0);
        do_mmas(1);
    }

    const int orow = bm + wm * 64 + (lane >> 2);
    const int ocol = bn + wn * 32 + (lane & 3) * 2;
    float bvx[4], bvy[4];
    if (BIAS) {
        #pragma unroll
        for (int j = 0; j < 4; j++) { bvx[j] = bias[ocol + j * 8]; bvy[j] = bias[ocol + j * 8 + 1]; }
    }
    #pragma unroll
    for (int i = 0; i < 4; i++) {
        const int rA = orow + i * 16;
        const int rB = rA + 8;
        int sA = 0, sB = 0;
        if (ROPE) { sA = rA % S_; sB = rB % S_; }
        #pragma unroll
        for (int j = 0; j < 4; j++) {
            const int cc = ocol + j * 8;
            float v0 = acc[i][j][0], v1 = acc[i][j][1];
            float v2 = acc[i][j][2], v3 = acc[i][j][3];
            if (ROPE && cc < 1024) {
                int m = (cc & 63) >> 1;
                float freq = exp2f(-(float)(m >> 1) * L2T_OVER16);
                float pA = (m & 1) ? (float)(sA / 7) : (float)(sA % 7);
                float pB = (m & 1) ? (float)(sB / 7) : (float)(sB % 7);
                float snA, csA, snB, csB;
                sincosf(pA * freq, &snA, &csA);
                sincosf(pB * freq, &snB, &csB);
                float t0 = v0 * csA - v1 * snA, t1 = v0 * snA + v1 * csA;
                float t2 = v2 * csB - v3 * snB, t3 = v2 * snB + v3 * csB;
                v0 = t0; v1 = t1; v2 = t2; v3 = t3;
            }
            if (BIAS) { v0 += bvx[j]; v1 += bvy[j]; v2 += bvx[j]; v3 += bvy[j]; }
            if (HALFOUT) {
                __half* Ch = (__half*)Cout;
                __half2 hA, hB;
                hA.x = __float2half_rn(v0); hA.y = __float2half_rn(v1);
                hB.x = __float2half_rn(v2); hB.y = __float2half_rn(v3);
                *(uint32_t*)(Ch + (size_t)rA * NCOLS + cc) = *(uint32_t*)&hA;
                *(uint32_t*)(Ch + (size_t)rB * NCOLS + cc) = *(uint32_t*)&hB;
            } else {
                float* Cf = (float*)Cout;
                *(float2*)(Cf + (size_t)rA * NCOLS + cc) = make_float2(v0, v1);
                *(float2*)(Cf + (size_t)rB * NCOLS + cc) = make_float2(v2, v3);
            }
        }
    }
}

// ---------------- tensor-core windowed attention (fp16 in) ----------------
// one block per (b,g,h), 128 threads / 4 warps; S=49 padded to 64.
// smem tiles (64 rows x 128B, xor swizzle): QH 0, KK 8192, VH 16384
#define T_QH 0u
#define T_KK 8192u
#define T_VH 16384u

__global__ __launch_bounds__(128) void attn_tc_kernel() {
    __shared__ __align__(1024) char sm[24576];
    const uint32_t sb = smem_u32(sm);

    const int tid  = threadIdx.x;
    const int lane = tid & 31;
    const int w    = tid >> 5;
    const int h    = blockIdx.x & 7;
    const int bg   = blockIdx.x >> 3;
    const size_t base = (size_t)bg * S_ * QKVN + h * 64;

    // zero-fill (padding rows must be 0)
    #pragma unroll
    for (int i = tid; i < 24576 / 16; i += 128)
        ((uint4*)sm)[i] = make_uint4(0, 0, 0, 0);
    __syncthreads();

    // fill rows 0..48: straight swizzled 16B copies (already fp16)
    for (int i = tid; i < S_ * 8; i += 128) {
        int s   = i >> 3;
        int seg = i & 7;                 // 16B chunk (8 halves)
        size_t ro = base + (size_t)s * QKVN + seg * 8;
        uint4 q = *(const uint4*)(g_qkv + ro);
        uint4 k = *(const uint4*)(g_qkv + ro + 512);
        uint4 v = *(const uint4*)(g_qkv + ro + 1024);
        uint32_t addr = (uint32_t)(s * 128 + ((seg ^ (s & 7)) << 4));
        *(uint4*)(sm + T_QH + addr) = q;
        *(uint4*)(sm + T_KK + addr) = k;
        *(uint4*)(sm + T_VH + addr) = v;
    }
    __syncthreads();

    // ---- QK^T: warp w -> score rows w*16..w*16+15, cols 0..63 ----
    const int a_r  = w * 16 + (lane & 15);
    const int a_cp = lane >> 4;
    const int b_r0 = (lane & 7) + ((lane & 16) >> 1);
    const int b_cp = (lane >> 3) & 1;

    float sc[8][4];
    #pragma unroll
    for (int j = 0; j < 8; j++)
        #pragma unroll
        for (int p = 0; p < 4; p++) sc[j][p] = 0.0f;

    #pragma unroll
    for (int ks = 0; ks < 4; ks++) {
        uint32_t aq[4], bk[4][4];
        {
            int ch = 2 * ks + a_cp;
            ldm4(aq, sb + T_QH + (uint32_t)(a_r * 128 + ((ch ^ (a_r & 7)) << 4)));
        }
        #pragma unroll
        for (int jn = 0; jn < 4; jn++) {
            int r  = jn * 16 + b_r0;
            int ch = 2 * ks + b_cp;
            ldm4(bk[jn], sb + T_KK + (uint32_t)(r * 128 + ((ch ^ (r & 7)) << 4)));
        }
        #pragma unroll
        for (int j = 0; j < 8; j++)
            mma16816(sc[j], aq, &bk[j >> 1][(j & 1) * 2]);
    }

    // ---- register softmax ----
    #pragma unroll
    for (int j = 0; j < 8; j++) {
        int t0 = j * 8 + 2 * (lane & 3);
        sc[j][0] = (t0     < S_) ? sc[j][0] * SCALE_ : -1e30f;
        sc[j][1] = (t0 + 1 < S_) ? sc[j][1] * SCALE_ : -1e30f;
        sc[j][2] = (t0     < S_) ? sc[j][2] * SCALE_ : -1e30f;
        sc[j][3] = (t0 + 1 < S_) ? sc[j][3] * SCALE_ : -1e30f;
    }
    float mx0 = -1e30f, mx1 = -1e30f;
    #pragma unroll
    for (int j = 0; j < 8; j++) {
        mx0 = fmaxf(mx0, fmaxf(sc[j][0], sc[j][1]));
        mx1 = fmaxf(mx1, fmaxf(sc[j][2], sc[j][3]));
    }
    mx0 = fmaxf(mx0, __shfl_xor_sync(0xffffffffu, mx0, 1));
    mx0 = fmaxf(mx0, __shfl_xor_sync(0xffffffffu, mx0, 2));
    mx1 = fmaxf(mx1, __shfl_xor_sync(0xffffffffu, mx1, 1));
    mx1 = fmaxf(mx1, __shfl_xor_sync(0xffffffffu, mx1, 2));
    float sum0 = 0.0f, sum1 = 0.0f;
    #pragma unroll
    for (int j = 0; j < 8; j++) {
        sc[j][0] = __expf(sc[j][0] - mx0);
        sc[j][1] = __expf(sc[j][1] - mx0);
        sc[j][2] = __expf(sc[j][2] - mx1);
        sc[j][3] = __expf(sc[j][3] - mx1);
        sum0 += sc[j][0] + sc[j][1];
        sum1 += sc[j][2] + sc[j][3];
    }
    sum0 += __shfl_xor_sync(0xffffffffu, sum0, 1);
    sum0 += __shfl_xor_sync(0xffffffffu, sum0, 2);
    sum1 += __shfl_xor_sync(0xffffffffu, sum1, 1);
    sum1 += __shfl_xor_sync(0xffffffffu, sum1, 2);

    // ---- pack P (unnormalized) as fp16 A fragments ----
    uint32_t pa[4][4];
    #pragma unroll
    for (int kt = 0; kt < 4; kt++) {
        __half2 t;
        t = __float22half2_rn(make_float2(sc[2*kt][0],   sc[2*kt][1]));   pa[kt][0] = *(uint32_t*)&t;
        t = __float22half2_rn(make_float2(sc[2*kt][2],   sc[2*kt][3]));   pa[kt][1] = *(uint32_t*)&t;
        t = __float22half2_rn(make_float2(sc[2*kt+1][0], sc[2*kt+1][1])); pa[kt][2] = *(uint32_t*)&t;
        t = __float22half2_rn(make_float2(sc[2*kt+1][2], sc[2*kt+1][3])); pa[kt][3] = *(uint32_t*)&t;
    }

    // ---- PV ----
    float oacc[8][4];
    #pragma unroll
    for (int nb = 0; nb < 8; nb++)
        #pragma unroll
        for (int p = 0; p < 4; p++) oacc[nb][p] = 0.0f;

    #pragma unroll
    for (int kt = 0; kt < 4; kt++) {
        uint32_t bv[4][4];
        #pragma unroll
        for (int ii = 0; ii < 4; ii++) {
            int rowk  = kt * 16 + ((lane >> 3) & 1) * 8 + (lane & 7);
            int chunk = 2 * ii + (lane >> 4);
            ldm4t(bv[ii], sb + T_VH + (uint32_t)(rowk * 128 + ((chunk ^ (rowk & 7)) << 4)));
        }
        #pragma unroll
        for (int nb = 0; nb < 8; nb++)
            mma16816(oacc[nb], pa[kt], &bv[nb >> 1][(nb & 1) * 2]);
    }

    // ---- normalize + scatter to (b,n,c), fp16 ----
    const float inv0 = 1.0f / sum0;
    const float inv1 = 1.0f / sum1;
    const int g = bg & 63;
    const int b = bg >> 6;
    const int s0 = w * 16 + (lane >> 2);
    const int s1 = s0 + 8;
    const int colb = 2 * (lane & 3);

    #pragma unroll
    for (int half = 0; half < 2; half++) {
        int s = half ? s1 : s0;
        if (s >= S_) continue;
        float inv = half ? inv1 : inv0;
        int sy = s / 7, sx = s - sy * 7;
        int n  = ((g >> 3) * 7 + sy) * 56 + (g & 7) * 7 + sx;
        size_t off = ((size_t)(b * NTOK + n)) * C_ + h * 64;
        #pragma unroll
        for (int nb = 0; nb < 8; nb++) {
            __half2 hv;
            hv.x = __float2half_rn(oacc[nb][half * 2]     * inv);
            hv.y = __float2half_rn(oacc[nb][half * 2 + 1] * inv);
            *(uint32_t*)(g_ah + off + nb * 8 + colb) = *(uint32_t*)&hv;
        }
    }
}

// ---------------- launch ----------------
extern "C" void kernel_launch(void* const* d_in, const int* in_sizes, int n_in,
                              void* d_out, int out_size)
{
    const float* x      = (const float*)d_in[0];
    const float* w_qkv  = (const float*)d_in[1];
    const float* w_proj = (const float*)d_in[2];
    const float* b_proj = (const float*)d_in[3];
    float* out = (float*)d_out;

    void *qkvp, *xhp, *whp, *php, *ahp;
    cudaGetSymbolAddress(&qkvp, g_qkv);
    cudaGetSymbolAddress(&xhp, g_xh);
    cudaGetSymbolAddress(&whp, g_wh);
    cudaGetSymbolAddress(&php, g_ph);
    cudaGetSymbolAddress(&ahp, g_ah);

    cudaFuncSetAttribute(mma_gemm<QKVN, false, true, true>,
                         cudaFuncAttributeMaxDynamicSharedMemorySize, DYN_SMEM);
    cudaFuncSetAttribute(mma_gemm<C_, true, false, false>,
                         cudaFuncAttributeMaxDynamicSharedMemorySize, DYN_SMEM);

    // 0) conversions
    conv_x_kernel<<<M_ * 128 / 256, 256>>>(x);
    conv_w_kernel<<<QKVN * C_ / 4 / 256, 256>>>(w_qkv, (__half*)whp);
    conv_w_kernel<<<C_ * C_ / 4 / 256, 256>>>(w_proj, (__half*)php);

    // 1) QKV GEMM (fp16 HMMA), fused RoPE, fp16 output
    dim3 g1(QKVN / 128, M_ / 128);
    mma_gemm<QKVN, false, true, true><<<g1, 256, DYN_SMEM>>>(
        (const __half*)xhp, (const __half*)whp, nullptr, qkvp);

    // 2) tensor-core windowed attention
    attn_tc_kernel<<<B_ * G_ * NH, 128>>>();

    // 3) projection GEMM + bias (fp16 HMMA, fp32 out)
    dim3 g2(C_ / 128, M_ / 128);
    mma_gemm<C_, true, false, false><<<g2, 256, DYN_SMEM>>>(
        (const __half*)ahp, (const __half*)php, b_proj, out);
}